// round 1
// baseline (speedup 1.0000x reference)
#include <cuda_runtime.h>

#define T_SEQ 2048
#define E_DIM 1024
#define H_NUM 16
#define L_DIM 64
#define NMID  1152   // 1024 q_lat cols + 64 latent_k + 64 latent_v

// ---------------- device scratch (no allocations allowed) ----------------
__device__ float g_W1[E_DIM * NMID];     // fused (Wq x q2l) ++ Wk^T ++ Wv^T
__device__ float g_W2[E_DIM * E_DIM];    // fused (v_up x Wout)
__device__ float g_mid[T_SEQ * NMID];    // [q_lat | latent_k | latent_v]
__device__ float g_ctx[T_SEQ * E_DIM];   // ctx_lat flattened [t, h*64+l]

// ---------------- prep 1: W1[e, h*64+l] = sum_d Wq[h*64+d, e] * q2l[h,d,l] ----
__global__ __launch_bounds__(256) void prep_w1_kernel(const float* __restrict__ Wq,
                                                      const float* __restrict__ q2l) {
    __shared__ float Wqs[64][65];   // [d][e-local]
    __shared__ float Qls[64][65];   // [d][l]
    const int h  = blockIdx.y;
    const int e0 = blockIdx.x * 64;
    const int tid = threadIdx.x, tx = tid & 15, ty = tid >> 4;

    #pragma unroll
    for (int i = 0; i < 16; i++) {
        int lin = tid + i * 256;
        int c = lin & 63, r = lin >> 6;
        Wqs[r][c] = Wq[(h * 64 + r) * E_DIM + e0 + c];
        Qls[r][c] = q2l[(h * 64 + r) * 64 + c];
    }
    __syncthreads();

    float acc[4][4];
    #pragma unroll
    for (int i = 0; i < 4; i++)
        #pragma unroll
        for (int j = 0; j < 4; j++) acc[i][j] = 0.f;

    #pragma unroll 8
    for (int d = 0; d < 64; d++) {
        float a[4], b[4];
        #pragma unroll
        for (int i = 0; i < 4; i++) a[i] = Wqs[d][ty * 4 + i];
        #pragma unroll
        for (int j = 0; j < 4; j++) b[j] = Qls[d][tx * 4 + j];
        #pragma unroll
        for (int i = 0; i < 4; i++)
            #pragma unroll
            for (int j = 0; j < 4; j++) acc[i][j] += a[i] * b[j];
    }
    #pragma unroll
    for (int i = 0; i < 4; i++) {
        float4 o = make_float4(acc[i][0], acc[i][1], acc[i][2], acc[i][3]);
        *(float4*)&g_W1[(e0 + ty * 4 + i) * NMID + h * 64 + tx * 4] = o;
    }
}

// ---------------- prep 2: transpose Wk_down / Wv_down into W1 tail columns ----
__global__ __launch_bounds__(256) void prep_kv_kernel(const float* __restrict__ Wk,
                                                      const float* __restrict__ Wv) {
    int idx = blockIdx.x * 256 + threadIdx.x;   // 64 * 1024
    int l = idx & 63, e = idx >> 6;
    g_W1[e * NMID + 1024 + l] = Wk[l * E_DIM + e];
    g_W1[e * NMID + 1088 + l] = Wv[l * E_DIM + e];
}

// ---------------- prep 3: W2[h*64+l, e] = sum_d v_up[h,l,d] * Wout[e, h*64+d] ----
__global__ __launch_bounds__(256) void prep_w2_kernel(const float* __restrict__ vup,
                                                      const float* __restrict__ Wout) {
    __shared__ __align__(16) float Wos[64][68];  // [e-local][d]
    __shared__ __align__(16) float Vus[64][68];  // [l][d]
    const int h  = blockIdx.y;
    const int e0 = blockIdx.x * 64;
    const int tid = threadIdx.x, tx = tid & 15, ty = tid >> 4;

    #pragma unroll
    for (int i = 0; i < 16; i++) {
        int lin = tid + i * 256;
        int c = lin & 63, r = lin >> 6;
        Wos[r][c] = Wout[(e0 + r) * E_DIM + h * 64 + c];
        Vus[r][c] = vup[(h * 64 + r) * 64 + c];
    }
    __syncthreads();

    float acc[4][4];
    #pragma unroll
    for (int i = 0; i < 4; i++)
        #pragma unroll
        for (int j = 0; j < 4; j++) acc[i][j] = 0.f;

    #pragma unroll
    for (int d4 = 0; d4 < 16; d4++) {
        float4 a[4], b[4];
        #pragma unroll
        for (int i = 0; i < 4; i++) a[i] = *(const float4*)&Vus[ty * 4 + i][d4 * 4];
        #pragma unroll
        for (int j = 0; j < 4; j++) b[j] = *(const float4*)&Wos[tx * 4 + j][d4 * 4];
        #pragma unroll
        for (int i = 0; i < 4; i++)
            #pragma unroll
            for (int j = 0; j < 4; j++)
                acc[i][j] += a[i].x * b[j].x + a[i].y * b[j].y +
                             a[i].z * b[j].z + a[i].w * b[j].w;
    }
    #pragma unroll
    for (int i = 0; i < 4; i++) {
        float4 o = make_float4(acc[i][0], acc[i][1], acc[i][2], acc[i][3]);
        *(float4*)&g_W2[(h * 64 + ty * 4 + i) * E_DIM + e0 + tx * 4] = o;
    }
}

// ---------------- generic fp32 GEMM: C[M,N] = A[M,K] @ B[K,N], row-major ----
// block tile 128(M) x 64(N), 256 threads, micro 8x4
__global__ __launch_bounds__(256) void gemm_kernel(const float* __restrict__ A,
                                                   const float* __restrict__ B,
                                                   float* __restrict__ C,
                                                   int M, int N, int K) {
    __shared__ __align__(16) float Ast[16][132];  // [k][m-local]
    __shared__ __align__(16) float Bs[16][68];    // [k][n-local]
    const int tid = threadIdx.x, tx = tid & 15, ty = tid >> 4;
    const int m0 = blockIdx.y * 128;
    const int n0 = blockIdx.x * 64;

    float acc[8][4];
    #pragma unroll
    for (int i = 0; i < 8; i++)
        #pragma unroll
        for (int j = 0; j < 4; j++) acc[i][j] = 0.f;

    for (int k0 = 0; k0 < K; k0 += 16) {
        #pragma unroll
        for (int i = 0; i < 8; i++) {
            int lin = tid + i * 256;
            int c = lin & 15, r = lin >> 4;
            Ast[c][r] = A[(m0 + r) * K + k0 + c];
        }
        #pragma unroll
        for (int i = 0; i < 4; i++) {
            int lin = tid + i * 256;
            int j = lin & 63, c = lin >> 6;
            Bs[c][j] = B[(k0 + c) * N + n0 + j];
        }
        __syncthreads();

        #pragma unroll
        for (int c = 0; c < 16; c++) {
            float4 a0 = *(const float4*)&Ast[c][ty * 8];
            float4 a1 = *(const float4*)&Ast[c][ty * 8 + 4];
            float4 bb = *(const float4*)&Bs[c][tx * 4];
            float av[8] = {a0.x, a0.y, a0.z, a0.w, a1.x, a1.y, a1.z, a1.w};
            float bv[4] = {bb.x, bb.y, bb.z, bb.w};
            #pragma unroll
            for (int i = 0; i < 8; i++)
                #pragma unroll
                for (int j = 0; j < 4; j++) acc[i][j] += av[i] * bv[j];
        }
        __syncthreads();
    }
    #pragma unroll
    for (int i = 0; i < 8; i++) {
        int row = m0 + ty * 8 + i;
        float4 o = make_float4(acc[i][0], acc[i][1], acc[i][2], acc[i][3]);
        *(float4*)&C[row * N + n0 + tx * 4] = o;
    }
}

// ---------------- flash attention over latent dim (L=64), causal ----------------
// grid: (32 q-tiles, 16 heads); block 256 threads (16x16), micro 4x4
#define ATTN_SMEM (3 * 64 * 68 * 4)
__global__ __launch_bounds__(256) void attn_kernel() {
    extern __shared__ __align__(16) float sm[];
    float (*Qs)[68] = (float(*)[68])sm;
    float (*Ks)[68] = (float(*)[68])(sm + 64 * 68);      // reused as P
    float (*Vs)[68] = (float(*)[68])(sm + 2 * 64 * 68);

    const int qt = (int)gridDim.x - 1 - (int)blockIdx.x;  // heavy tiles first
    const int h  = blockIdx.y;
    const int tid = threadIdx.x, tx = tid & 15, ty = tid >> 4;
    const int q0 = qt * 64;

    // load Q tile (pre-scaled by 1/sqrt(L) = 0.125)
    #pragma unroll
    for (int i = 0; i < 16; i++) {
        int lin = tid + i * 256;
        int l = lin & 63, r = lin >> 6;
        Qs[r][l] = g_mid[(q0 + r) * NMID + h * 64 + l] * 0.125f;
    }

    float acc[4][4];
    float mrow[4], lrow[4];
    #pragma unroll
    for (int i = 0; i < 4; i++) {
        mrow[i] = -1e30f; lrow[i] = 0.f;
        #pragma unroll
        for (int j = 0; j < 4; j++) acc[i][j] = 0.f;
    }

    for (int kb = 0; kb <= qt; kb++) {
        const int s0 = kb * 64;
        __syncthreads();   // previous iter's reads of Ks(P)/Vs done
        #pragma unroll
        for (int i = 0; i < 16; i++) {
            int lin = tid + i * 256;
            int l = lin & 63, r = lin >> 6;
            const float* src = &g_mid[(s0 + r) * NMID + 1024];
            Ks[r][l] = src[l];
            Vs[r][l] = src[64 + l];
        }
        __syncthreads();

        // S = Q @ K^T
        float s[4][4];
        #pragma unroll
        for (int i = 0; i < 4; i++)
            #pragma unroll
            for (int j = 0; j < 4; j++) s[i][j] = 0.f;
        #pragma unroll
        for (int l4 = 0; l4 < 16; l4++) {
            float4 q[4], k[4];
            #pragma unroll
            for (int i = 0; i < 4; i++) q[i] = *(const float4*)&Qs[ty * 4 + i][l4 * 4];
            #pragma unroll
            for (int j = 0; j < 4; j++) k[j] = *(const float4*)&Ks[tx * 4 + j][l4 * 4];
            #pragma unroll
            for (int i = 0; i < 4; i++)
                #pragma unroll
                for (int j = 0; j < 4; j++)
                    s[i][j] += q[i].x * k[j].x + q[i].y * k[j].y +
                               q[i].z * k[j].z + q[i].w * k[j].w;
        }
        __syncthreads();   // all threads done reading Ks before overwriting with P

        // causal mask on the diagonal block
        if (kb == qt) {
            #pragma unroll
            for (int i = 0; i < 4; i++)
                #pragma unroll
                for (int j = 0; j < 4; j++)
                    if (s0 + tx * 4 + j > q0 + ty * 4 + i) s[i][j] = -1e30f;
        }

        // online softmax (row groups = 16 lanes via width-16 shfl)
        float alpha[4];
        #pragma unroll
        for (int i = 0; i < 4; i++) {
            float rm = fmaxf(fmaxf(s[i][0], s[i][1]), fmaxf(s[i][2], s[i][3]));
            #pragma unroll
            for (int off = 8; off > 0; off >>= 1)
                rm = fmaxf(rm, __shfl_xor_sync(0xffffffffu, rm, off, 16));
            float mnew = fmaxf(mrow[i], rm);
            alpha[i] = __expf(mrow[i] - mnew);
            mrow[i] = mnew;
            float rs = 0.f;
            #pragma unroll
            for (int j = 0; j < 4; j++) { s[i][j] = __expf(s[i][j] - mnew); rs += s[i][j]; }
            #pragma unroll
            for (int off = 8; off > 0; off >>= 1)
                rs += __shfl_xor_sync(0xffffffffu, rs, off, 16);
            lrow[i] = lrow[i] * alpha[i] + rs;
        }

        // stage P into Ks buffer
        #pragma unroll
        for (int i = 0; i < 4; i++)
            #pragma unroll
            for (int j = 0; j < 4; j++) Ks[ty * 4 + i][tx * 4 + j] = s[i][j];
        __syncthreads();

        // O = O*alpha + P @ V
        #pragma unroll
        for (int i = 0; i < 4; i++)
            #pragma unroll
            for (int j = 0; j < 4; j++) acc[i][j] *= alpha[i];
        #pragma unroll
        for (int k4 = 0; k4 < 16; k4++) {
            float4 p[4], v[4];
            #pragma unroll
            for (int i = 0; i < 4; i++) p[i] = *(const float4*)&Ks[ty * 4 + i][k4 * 4];
            #pragma unroll
            for (int kk = 0; kk < 4; kk++) v[kk] = *(const float4*)&Vs[k4 * 4 + kk][tx * 4];
            #pragma unroll
            for (int i = 0; i < 4; i++) {
                acc[i][0] += p[i].x * v[0].x + p[i].y * v[1].x + p[i].z * v[2].x + p[i].w * v[3].x;
                acc[i][1] += p[i].x * v[0].y + p[i].y * v[1].y + p[i].z * v[2].y + p[i].w * v[3].y;
                acc[i][2] += p[i].x * v[0].z + p[i].y * v[1].z + p[i].z * v[2].z + p[i].w * v[3].z;
                acc[i][3] += p[i].x * v[0].w + p[i].y * v[1].w + p[i].z * v[2].w + p[i].w * v[3].w;
            }
        }
    }

    // normalize + write ctx
    #pragma unroll
    for (int i = 0; i < 4; i++) {
        float inv = 1.0f / lrow[i];
        float4 o = make_float4(acc[i][0] * inv, acc[i][1] * inv,
                               acc[i][2] * inv, acc[i][3] * inv);
        *(float4*)&g_ctx[(q0 + ty * 4 + i) * E_DIM + h * 64 + tx * 4] = o;
    }
}

// ---------------- launch ----------------
extern "C" void kernel_launch(void* const* d_in, const int* in_sizes, int n_in,
                              void* d_out, int out_size) {
    const float* hidden = (const float*)d_in[0];
    const float* Wq     = (const float*)d_in[1];
    const float* Wk     = (const float*)d_in[2];
    const float* Wv     = (const float*)d_in[3];
    const float* q2l    = (const float*)d_in[4];
    const float* vup    = (const float*)d_in[5];
    const float* Wout   = (const float*)d_in[6];
    float* out = (float*)d_out;

    void *w1p, *w2p, *midp, *ctxp;
    cudaGetSymbolAddress(&w1p,  g_W1);
    cudaGetSymbolAddress(&w2p,  g_W2);
    cudaGetSymbolAddress(&midp, g_mid);
    cudaGetSymbolAddress(&ctxp, g_ctx);

    cudaFuncSetAttribute(attn_kernel, cudaFuncAttributeMaxDynamicSharedMemorySize, ATTN_SMEM);

    // weight fusion preps
    prep_w1_kernel<<<dim3(16, 16), 256>>>(Wq, q2l);
    prep_kv_kernel<<<256, 256>>>(Wk, Wv);
    prep_w2_kernel<<<dim3(16, 16), 256>>>(vup, Wout);

    // mid = hidden @ W1   (2048 x 1152 x 1024)
    gemm_kernel<<<dim3(NMID / 64, T_SEQ / 128), 256>>>(hidden, (const float*)w1p,
                                                       (float*)midp, T_SEQ, NMID, E_DIM);
    // flash attention over latent K/V
    attn_kernel<<<dim3(T_SEQ / 64, H_NUM), 256, ATTN_SMEM>>>();

    // out = ctx @ W2   (2048 x 1024 x 1024)
    gemm_kernel<<<dim3(E_DIM / 64, T_SEQ / 128), 256>>>((const float*)ctxp, (const float*)w2p,
                                                        out, T_SEQ, E_DIM, E_DIM);
}

// round 4
// speedup vs baseline: 2.4059x; 2.4059x over previous
#include <cuda_runtime.h>
#include <cstdint>

#define T_SEQ 2048
#define E_DIM 1024
#define H_NUM 16
#define L_DIM 64
#define NMID  1152   // 1024 q_lat cols + 64 latent_k + 64 latent_v

// ==================== portable tensor-core helpers (sm_80+) ====================
// tf32 round-to-nearest of fp32; returns tf32 bit pattern
__device__ __forceinline__ uint32_t f2tf32(float x) {
    uint32_t b;
    asm("cvt.rna.tf32.f32 %0, %1;" : "=r"(b) : "f"(x));
    return b;
}

// D(16x8,fp32) += A(16x8,tf32) * B(8x8,tf32)
__device__ __forceinline__ void mma_tf32(float* c, const uint32_t* a, uint32_t b0, uint32_t b1) {
    asm volatile(
        "mma.sync.aligned.m16n8k8.row.col.f32.tf32.tf32.f32 "
        "{%0,%1,%2,%3}, {%4,%5,%6,%7}, {%8,%9}, {%0,%1,%2,%3};"
        : "+f"(c[0]), "+f"(c[1]), "+f"(c[2]), "+f"(c[3])
        : "r"(a[0]), "r"(a[1]), "r"(a[2]), "r"(a[3]), "r"(b0), "r"(b1));
}

// ==================== device scratch ====================
__device__ float g_W1T[NMID * E_DIM];    // B^T for GEMM1: [n][k]
__device__ float g_W2T[E_DIM * E_DIM];   // B^T for GEMM2
__device__ float g_mid[T_SEQ * NMID];    // [q_lat | latent_k | latent_v]
__device__ float g_ctx[T_SEQ * E_DIM];   // ctx_lat flattened [t, h*64+l]

// ---------------- prep 1: W1T[h*64+l][e] = sum_d Wq[h*64+d, e] * q2l[h,d,l] ----
__global__ __launch_bounds__(256) void prep_w1_kernel(const float* __restrict__ Wq,
                                                      const float* __restrict__ q2l) {
    __shared__ float Wqs[64][65];   // [d][e-local]
    __shared__ float Qls[64][65];   // [d][l]
    const int h  = blockIdx.y;
    const int e0 = blockIdx.x * 64;
    const int tid = threadIdx.x, tx = tid & 15, ty = tid >> 4;

    #pragma unroll
    for (int i = 0; i < 16; i++) {
        int lin = tid + i * 256;
        int c = lin & 63, r = lin >> 6;
        Wqs[r][c] = Wq[(h * 64 + r) * E_DIM + e0 + c];
        Qls[r][c] = q2l[(h * 64 + r) * 64 + c];
    }
    __syncthreads();

    float acc[4][4];
    #pragma unroll
    for (int i = 0; i < 4; i++)
        #pragma unroll
        for (int j = 0; j < 4; j++) acc[i][j] = 0.f;

    #pragma unroll 8
    for (int d = 0; d < 64; d++) {
        float a[4], b[4];
        #pragma unroll
        for (int i = 0; i < 4; i++) a[i] = Wqs[d][ty * 4 + i];
        #pragma unroll
        for (int j = 0; j < 4; j++) b[j] = Qls[d][tx * 4 + j];
        #pragma unroll
        for (int i = 0; i < 4; i++)
            #pragma unroll
            for (int j = 0; j < 4; j++) acc[i][j] += a[i] * b[j];
    }
    #pragma unroll
    for (int j = 0; j < 4; j++)
        #pragma unroll
        for (int i = 0; i < 4; i++)
            g_W1T[(h * 64 + tx * 4 + j) * E_DIM + e0 + ty * 4 + i] = acc[i][j];
}

// ---------------- prep 2: W1T rows 1024+l / 1088+l are Wk_down / Wv_down ----
__global__ __launch_bounds__(256) void prep_kv_kernel(const float* __restrict__ Wk,
                                                      const float* __restrict__ Wv) {
    int idx = blockIdx.x * 256 + threadIdx.x;   // 64 * 1024
    g_W1T[1024 * E_DIM + idx] = Wk[idx];
    g_W1T[1088 * E_DIM + idx] = Wv[idx];
}

// ---------------- prep 3: W2T[e][h*64+l] = sum_d v_up[h,l,d] * Wout[e, h*64+d] ----
__global__ __launch_bounds__(256) void prep_w2_kernel(const float* __restrict__ vup,
                                                      const float* __restrict__ Wout) {
    __shared__ __align__(16) float Wos[64][68];  // [e-local][d]
    __shared__ __align__(16) float Vus[64][68];  // [l][d]
    const int h  = blockIdx.y;
    const int e0 = blockIdx.x * 64;
    const int tid = threadIdx.x, tx = tid & 15, ty = tid >> 4;

    #pragma unroll
    for (int i = 0; i < 16; i++) {
        int lin = tid + i * 256;
        int c = lin & 63, r = lin >> 6;
        Wos[r][c] = Wout[(e0 + r) * E_DIM + h * 64 + c];
        Vus[r][c] = vup[(h * 64 + r) * 64 + c];
    }
    __syncthreads();

    float acc[4][4];
    #pragma unroll
    for (int i = 0; i < 4; i++)
        #pragma unroll
        for (int j = 0; j < 4; j++) acc[i][j] = 0.f;

    #pragma unroll
    for (int d4 = 0; d4 < 16; d4++) {
        float4 a[4], b[4];
        #pragma unroll
        for (int i = 0; i < 4; i++) a[i] = *(const float4*)&Vus[ty * 4 + i][d4 * 4];
        #pragma unroll
        for (int j = 0; j < 4; j++) b[j] = *(const float4*)&Wos[tx * 4 + j][d4 * 4];
        #pragma unroll
        for (int i = 0; i < 4; i++)
            #pragma unroll
            for (int j = 0; j < 4; j++)
                acc[i][j] += a[i].x * b[j].x + a[i].y * b[j].y +
                             a[i].z * b[j].z + a[i].w * b[j].w;
    }
    #pragma unroll
    for (int j = 0; j < 4; j++)
        #pragma unroll
        for (int i = 0; i < 4; i++)
            g_W2T[(e0 + tx * 4 + j) * E_DIM + h * 64 + ty * 4 + i] = acc[i][j];
}

// ==================== 3xTF32 mma.sync GEMM ====================
// C[M,N] = A[M,K] @ BT[N,K]^T.  CTA tile 128x128, 256 threads (8 warps, 4x2).
// Warp tile 32(M) x 64(N).  K staged in 32-chunks, split hi/lo in smem.
#define GPAD 36
#define G_AH 0
#define G_AL (128 * GPAD)
#define G_BH (2 * 128 * GPAD)
#define G_BL (3 * 128 * GPAD)
#define GEMM_SMEM (4 * 128 * GPAD * 4)

__global__ __launch_bounds__(256, 2) void gemm_mma(const float* __restrict__ A,
                                                   const float* __restrict__ BT,
                                                   float* __restrict__ C,
                                                   int N, int K) {
    extern __shared__ uint32_t gsm[];
    const int tid = threadIdx.x;
    const int wid = tid >> 5, lane = tid & 31;
    const int g = lane >> 2, tig = lane & 3;
    const int wm = wid & 3, wn = wid >> 2;       // 4 m-strips x 2 n-strips
    const int m0 = blockIdx.y * 128;
    const int n0 = blockIdx.x * 128;

    float c[2][8][4];
    #pragma unroll
    for (int mt = 0; mt < 2; mt++)
        #pragma unroll
        for (int nt = 0; nt < 8; nt++)
            #pragma unroll
            for (int j = 0; j < 4; j++) c[mt][nt][j] = 0.f;

    for (int k0 = 0; k0 < K; k0 += 32) {
        __syncthreads();
        // stage + tf32 split: A[128][32], BT[128][32]
        #pragma unroll
        for (int i = 0; i < 4; i++) {
            int lin = tid + i * 256;               // 1024 float4 slots
            int row = lin >> 3, cc = lin & 7;
            float4 va = *(const float4*)&A[(size_t)(m0 + row) * K + k0 + cc * 4];
            float4 vb = *(const float4*)&BT[(size_t)(n0 + row) * K + k0 + cc * 4];
            uint32_t* ah = &gsm[G_AH + row * GPAD + cc * 4];
            uint32_t* al = &gsm[G_AL + row * GPAD + cc * 4];
            uint32_t* bh = &gsm[G_BH + row * GPAD + cc * 4];
            uint32_t* bl = &gsm[G_BL + row * GPAD + cc * 4];
            float vv[4] = {va.x, va.y, va.z, va.w};
            float ww[4] = {vb.x, vb.y, vb.z, vb.w};
            #pragma unroll
            for (int q = 0; q < 4; q++) {
                uint32_t hi = f2tf32(vv[q]);
                ah[q] = hi; al[q] = f2tf32(vv[q] - __uint_as_float(hi));
                hi = f2tf32(ww[q]);
                bh[q] = hi; bl[q] = f2tf32(ww[q] - __uint_as_float(hi));
            }
        }
        __syncthreads();

        #pragma unroll
        for (int ks = 0; ks < 4; ks++) {
            uint32_t ah[2][4], al[2][4];
            #pragma unroll
            for (int mt = 0; mt < 2; mt++) {
                int r0 = (wm * 32 + mt * 16 + g) * GPAD + ks * 8 + tig;
                int r1 = (wm * 32 + mt * 16 + g + 8) * GPAD + ks * 8 + tig;
                ah[mt][0] = gsm[G_AH + r0]; ah[mt][1] = gsm[G_AH + r1];
                ah[mt][2] = gsm[G_AH + r0 + 4]; ah[mt][3] = gsm[G_AH + r1 + 4];
                al[mt][0] = gsm[G_AL + r0]; al[mt][1] = gsm[G_AL + r1];
                al[mt][2] = gsm[G_AL + r0 + 4]; al[mt][3] = gsm[G_AL + r1 + 4];
            }
            #pragma unroll
            for (int nt = 0; nt < 8; nt++) {
                int rb = (wn * 64 + nt * 8 + g) * GPAD + ks * 8 + tig;
                uint32_t bh0 = gsm[G_BH + rb], bh1 = gsm[G_BH + rb + 4];
                uint32_t bl0 = gsm[G_BL + rb], bl1 = gsm[G_BL + rb + 4];
                #pragma unroll
                for (int mt = 0; mt < 2; mt++) {
                    mma_tf32(c[mt][nt], ah[mt], bh0, bh1);
                    mma_tf32(c[mt][nt], ah[mt], bl0, bl1);
                    mma_tf32(c[mt][nt], al[mt], bh0, bh1);
                }
            }
        }
    }

    // epilogue
    #pragma unroll
    for (int mt = 0; mt < 2; mt++) {
        int row0 = m0 + wm * 32 + mt * 16 + g;
        #pragma unroll
        for (int nt = 0; nt < 8; nt++) {
            int col = n0 + wn * 64 + nt * 8 + 2 * tig;
            *(float2*)&C[(size_t)row0 * N + col]       = make_float2(c[mt][nt][0], c[mt][nt][1]);
            *(float2*)&C[(size_t)(row0 + 8) * N + col] = make_float2(c[mt][nt][2], c[mt][nt][3]);
        }
    }
}

// ==================== tf32 mma.sync flash attention ====================
// CTA: 128-query tile, 8 warps x 16 rows.  KV tiles of 64, latent dim L=64.
// smem (uint32 tf32 bits): Qs[128][68], Ks[64][68], Vs[64][72], Ps[8][16][68]
#define QS_OFF 0
#define KS_OFF (128 * 68)
#define VS_OFF (KS_OFF + 64 * 68)
#define PS_OFF (VS_OFF + 64 * 72)
#define ATTN_SMEM ((PS_OFF + 8 * 16 * 68) * 4)

__global__ __launch_bounds__(256, 1) void attn_mma() {
    extern __shared__ uint32_t sm[];
    const int tid = threadIdx.x;
    const int wid = tid >> 5, lane = tid & 31;
    const int g = lane >> 2, tig = lane & 3;
    const int wq = wid * 16;
    const int qt = (int)gridDim.x - 1 - (int)blockIdx.x;  // heavy first
    const int h  = blockIdx.y;
    const int q0 = qt * 128;

    // stage Q (scaled by 1/sqrt(L)=0.125, tf32-rounded)
    #pragma unroll
    for (int i = 0; i < 8; i++) {
        int lin = tid + i * 256;                  // 2048 float4 slots
        int r = lin >> 4, c4 = lin & 15;
        float4 v = *(const float4*)&g_mid[(size_t)(q0 + r) * NMID + h * 64 + c4 * 4];
        uint32_t* dst = &sm[QS_OFF + r * 68 + c4 * 4];
        dst[0] = f2tf32(v.x * 0.125f); dst[1] = f2tf32(v.y * 0.125f);
        dst[2] = f2tf32(v.z * 0.125f); dst[3] = f2tf32(v.w * 0.125f);
    }
    __syncthreads();

    // preload Q A-fragments (constant across kv tiles): 8 k-steps x 4 regs
    uint32_t qa[8][4];
    #pragma unroll
    for (int ks = 0; ks < 8; ks++) {
        int r0 = (wq + g) * 68 + ks * 8 + tig;
        int r1 = (wq + g + 8) * 68 + ks * 8 + tig;
        qa[ks][0] = sm[QS_OFF + r0]; qa[ks][1] = sm[QS_OFF + r1];
        qa[ks][2] = sm[QS_OFF + r0 + 4]; qa[ks][3] = sm[QS_OFF + r1 + 4];
    }

    float o[8][4];
    #pragma unroll
    for (int nt = 0; nt < 8; nt++)
        #pragma unroll
        for (int j = 0; j < 4; j++) o[nt][j] = 0.f;
    float m0r = -1e30f, m1r = -1e30f, l0r = 0.f, l1r = 0.f;

    uint32_t* Pw = &sm[PS_OFF + wid * 16 * 68];
    const int nkv = 2 * qt + 2;

    for (int kb = 0; kb < nkv; kb++) {
        const int s0 = kb * 64;
        __syncthreads();
        // stage K and V tiles (tf32)
        #pragma unroll
        for (int i = 0; i < 4; i++) {
            int lin = tid + i * 256;               // 1024 float4 slots
            int r = lin >> 4, c4 = lin & 15;
            const float* src = &g_mid[(size_t)(s0 + r) * NMID + 1024];
            float4 kv = *(const float4*)&src[c4 * 4];
            float4 vv = *(const float4*)&src[64 + c4 * 4];
            uint32_t* kd = &sm[KS_OFF + r * 68 + c4 * 4];
            uint32_t* vd = &sm[VS_OFF + r * 72 + c4 * 4];
            kd[0] = f2tf32(kv.x); kd[1] = f2tf32(kv.y); kd[2] = f2tf32(kv.z); kd[3] = f2tf32(kv.w);
            vd[0] = f2tf32(vv.x); vd[1] = f2tf32(vv.y); vd[2] = f2tf32(vv.z); vd[3] = f2tf32(vv.w);
        }
        __syncthreads();

        // S = Q @ K^T   (16 x 64 per warp)
        float s[8][4];
        #pragma unroll
        for (int nt = 0; nt < 8; nt++) {
            s[nt][0] = s[nt][1] = s[nt][2] = s[nt][3] = 0.f;
            #pragma unroll
            for (int ks = 0; ks < 8; ks++) {
                int rb = (nt * 8 + g) * 68 + ks * 8 + tig;
                mma_tf32(s[nt], qa[ks], sm[KS_OFF + rb], sm[KS_OFF + rb + 4]);
            }
        }

        // causal mask (only possible on last two tiles)
        if (kb >= 2 * qt) {
            int row0 = q0 + wq + g, row1 = row0 + 8;
            #pragma unroll
            for (int nt = 0; nt < 8; nt++) {
                int c0 = s0 + nt * 8 + 2 * tig;
                if (c0     > row0) s[nt][0] = -1e30f;
                if (c0 + 1 > row0) s[nt][1] = -1e30f;
                if (c0     > row1) s[nt][2] = -1e30f;
                if (c0 + 1 > row1) s[nt][3] = -1e30f;
            }
        }

        // online softmax (rows g and g+8; reduce across quad lanes tig=0..3)
        float rm0 = -1e30f, rm1 = -1e30f;
        #pragma unroll
        for (int nt = 0; nt < 8; nt++) {
            rm0 = fmaxf(rm0, fmaxf(s[nt][0], s[nt][1]));
            rm1 = fmaxf(rm1, fmaxf(s[nt][2], s[nt][3]));
        }
        rm0 = fmaxf(rm0, __shfl_xor_sync(0xffffffffu, rm0, 1));
        rm0 = fmaxf(rm0, __shfl_xor_sync(0xffffffffu, rm0, 2));
        rm1 = fmaxf(rm1, __shfl_xor_sync(0xffffffffu, rm1, 1));
        rm1 = fmaxf(rm1, __shfl_xor_sync(0xffffffffu, rm1, 2));
        float mn0 = fmaxf(m0r, rm0), mn1 = fmaxf(m1r, rm1);
        float al0 = __expf(m0r - mn0), al1 = __expf(m1r - mn1);
        m0r = mn0; m1r = mn1;

        float rs0 = 0.f, rs1 = 0.f;
        #pragma unroll
        for (int nt = 0; nt < 8; nt++) {
            s[nt][0] = __expf(s[nt][0] - mn0); rs0 += s[nt][0];
            s[nt][1] = __expf(s[nt][1] - mn0); rs0 += s[nt][1];
            s[nt][2] = __expf(s[nt][2] - mn1); rs1 += s[nt][2];
            s[nt][3] = __expf(s[nt][3] - mn1); rs1 += s[nt][3];
        }
        rs0 += __shfl_xor_sync(0xffffffffu, rs0, 1);
        rs0 += __shfl_xor_sync(0xffffffffu, rs0, 2);
        rs1 += __shfl_xor_sync(0xffffffffu, rs1, 1);
        rs1 += __shfl_xor_sync(0xffffffffu, rs1, 2);
        l0r = l0r * al0 + rs0;
        l1r = l1r * al1 + rs1;

        // stage P (tf32) into per-warp smem region (C-frag -> A-frag reshape)
        #pragma unroll
        for (int nt = 0; nt < 8; nt++) {
            int cc = nt * 8 + 2 * tig;
            Pw[g * 68 + cc]           = f2tf32(s[nt][0]);
            Pw[g * 68 + cc + 1]       = f2tf32(s[nt][1]);
            Pw[(g + 8) * 68 + cc]     = f2tf32(s[nt][2]);
            Pw[(g + 8) * 68 + cc + 1] = f2tf32(s[nt][3]);
        }
        __syncwarp();

        // O = O*alpha + P @ V
        #pragma unroll
        for (int nt = 0; nt < 8; nt++) {
            o[nt][0] *= al0; o[nt][1] *= al0;
            o[nt][2] *= al1; o[nt][3] *= al1;
        }
        #pragma unroll
        for (int ks = 0; ks < 8; ks++) {
            uint32_t pa[4];
            int kc = ks * 8 + tig;
            pa[0] = Pw[g * 68 + kc];     pa[1] = Pw[(g + 8) * 68 + kc];
            pa[2] = Pw[g * 68 + kc + 4]; pa[3] = Pw[(g + 8) * 68 + kc + 4];
            #pragma unroll
            for (int nt = 0; nt < 8; nt++) {
                uint32_t v0 = sm[VS_OFF + (ks * 8 + tig) * 72 + nt * 8 + g];
                uint32_t v1 = sm[VS_OFF + (ks * 8 + tig + 4) * 72 + nt * 8 + g];
                mma_tf32(o[nt], pa, v0, v1);
            }
        }
        __syncwarp();
    }

    // normalize + write ctx
    float inv0 = 1.0f / l0r, inv1 = 1.0f / l1r;
    int row0 = q0 + wq + g;
    #pragma unroll
    for (int nt = 0; nt < 8; nt++) {
        int col = h * 64 + nt * 8 + 2 * tig;
        *(float2*)&g_ctx[(size_t)row0 * E_DIM + col] =
            make_float2(o[nt][0] * inv0, o[nt][1] * inv0);
        *(float2*)&g_ctx[(size_t)(row0 + 8) * E_DIM + col] =
            make_float2(o[nt][2] * inv1, o[nt][3] * inv1);
    }
}

// ---------------- launch ----------------
extern "C" void kernel_launch(void* const* d_in, const int* in_sizes, int n_in,
                              void* d_out, int out_size) {
    const float* hidden = (const float*)d_in[0];
    const float* Wq     = (const float*)d_in[1];
    const float* Wk     = (const float*)d_in[2];
    const float* Wv     = (const float*)d_in[3];
    const float* q2l    = (const float*)d_in[4];
    const float* vup    = (const float*)d_in[5];
    const float* Wout   = (const float*)d_in[6];
    float* out = (float*)d_out;

    void *w1p, *w2p, *midp;
    cudaGetSymbolAddress(&w1p,  g_W1T);
    cudaGetSymbolAddress(&w2p,  g_W2T);
    cudaGetSymbolAddress(&midp, g_mid);
    void* ctxp;
    cudaGetSymbolAddress(&ctxp, g_ctx);

    cudaFuncSetAttribute(gemm_mma, cudaFuncAttributeMaxDynamicSharedMemorySize, GEMM_SMEM);
    cudaFuncSetAttribute(attn_mma, cudaFuncAttributeMaxDynamicSharedMemorySize, ATTN_SMEM);

    // weight fusion preps (emit B transposed: [N][K] K-major)
    prep_w1_kernel<<<dim3(16, 16), 256>>>(Wq, q2l);
    prep_kv_kernel<<<256, 256>>>(Wk, Wv);
    prep_w2_kernel<<<dim3(16, 16), 256>>>(vup, Wout);

    // mid = hidden @ W1   (2048 x 1152 x 1024), 3xTF32 mma.sync
    gemm_mma<<<dim3(NMID / 128, T_SEQ / 128), 256, GEMM_SMEM>>>(
        hidden, (const float*)w1p, (float*)midp, NMID, E_DIM);

    // flash attention over latent K/V, tf32 mma.sync
    attn_mma<<<dim3(T_SEQ / 128, H_NUM), 256, ATTN_SMEM>>>();

    // out = ctx @ W2   (2048 x 1024 x 1024), 3xTF32 mma.sync
    gemm_mma<<<dim3(E_DIM / 128, T_SEQ / 128), 256, GEMM_SMEM>>>(
        (const float*)ctxp, (const float*)w2p, out, E_DIM, E_DIM);
}

// round 6
// speedup vs baseline: 2.4492x; 1.0180x over previous
#include <cuda_runtime.h>
#include <cstdint>

#define T_SEQ 2048
#define E_DIM 1024
#define H_NUM 16
#define L_DIM 64
#define NMID  1152   // 1024 q_lat cols + 64 latent_k + 64 latent_v

// ==================== helpers ====================
__device__ __forceinline__ uint32_t f2tf32(float x) {
    uint32_t b;
    asm("cvt.rna.tf32.f32 %0, %1;" : "=r"(b) : "f"(x));
    return b;
}

// D(16x8,fp32) += A(16x8,tf32) * B(8x8,tf32)
__device__ __forceinline__ void mma_tf32(float* c, const uint32_t* a, uint32_t b0, uint32_t b1) {
    asm volatile(
        "mma.sync.aligned.m16n8k8.row.col.f32.tf32.tf32.f32 "
        "{%0,%1,%2,%3}, {%4,%5,%6,%7}, {%8,%9}, {%0,%1,%2,%3};"
        : "+f"(c[0]), "+f"(c[1]), "+f"(c[2]), "+f"(c[3])
        : "r"(a[0]), "r"(a[1]), "r"(a[2]), "r"(a[3]), "r"(b0), "r"(b1));
}

__device__ __forceinline__ uint32_t smem_u32(const void* p) {
    uint32_t a;
    asm("{ .reg .u64 t; cvta.to.shared.u64 t, %1; cvt.u32.u64 %0, t; }" : "=r"(a) : "l"(p));
    return a;
}

__device__ __forceinline__ void cp_async16(uint32_t dst, const void* src) {
    asm volatile("cp.async.cg.shared.global [%0], [%1], 16;" :: "r"(dst), "l"(src));
}
#define CP_COMMIT()  asm volatile("cp.async.commit_group;" ::: "memory")
#define CP_WAIT(N)   asm volatile("cp.async.wait_group %0;" :: "n"(N) : "memory")

// split fp32 -> (tf32 hi bits, tf32 lo bits)
__device__ __forceinline__ void tf32_split(float x, uint32_t& hi, uint32_t& lo) {
    hi = f2tf32(x);
    lo = f2tf32(x - __uint_as_float(hi));
}

// ==================== device scratch ====================
__device__ float g_W1T[NMID * E_DIM];    // B^T for GEMM1: [n][k]
__device__ float g_W2T[E_DIM * E_DIM];   // B^T for GEMM2
__device__ float g_mid[T_SEQ * NMID];    // [q_lat | latent_k | latent_v]
__device__ float g_ctx[T_SEQ * E_DIM];   // ctx_lat flattened [t, h*64+l]

// ---------------- prep 1 ----------------
__global__ __launch_bounds__(256) void prep_w1_kernel(const float* __restrict__ Wq,
                                                      const float* __restrict__ q2l) {
    __shared__ float Wqs[64][65];
    __shared__ float Qls[64][65];
    const int h  = blockIdx.y;
    const int e0 = blockIdx.x * 64;
    const int tid = threadIdx.x, tx = tid & 15, ty = tid >> 4;

    #pragma unroll
    for (int i = 0; i < 16; i++) {
        int lin = tid + i * 256;
        int c = lin & 63, r = lin >> 6;
        Wqs[r][c] = Wq[(h * 64 + r) * E_DIM + e0 + c];
        Qls[r][c] = q2l[(h * 64 + r) * 64 + c];
    }
    __syncthreads();

    float acc[4][4];
    #pragma unroll
    for (int i = 0; i < 4; i++)
        #pragma unroll
        for (int j = 0; j < 4; j++) acc[i][j] = 0.f;

    #pragma unroll 8
    for (int d = 0; d < 64; d++) {
        float a[4], b[4];
        #pragma unroll
        for (int i = 0; i < 4; i++) a[i] = Wqs[d][ty * 4 + i];
        #pragma unroll
        for (int j = 0; j < 4; j++) b[j] = Qls[d][tx * 4 + j];
        #pragma unroll
        for (int i = 0; i < 4; i++)
            #pragma unroll
            for (int j = 0; j < 4; j++) acc[i][j] += a[i] * b[j];
    }
    #pragma unroll
    for (int j = 0; j < 4; j++)
        #pragma unroll
        for (int i = 0; i < 4; i++)
            g_W1T[(h * 64 + tx * 4 + j) * E_DIM + e0 + ty * 4 + i] = acc[i][j];
}

// ---------------- prep 2 ----------------
__global__ __launch_bounds__(256) void prep_kv_kernel(const float* __restrict__ Wk,
                                                      const float* __restrict__ Wv) {
    int idx = blockIdx.x * 256 + threadIdx.x;   // 64 * 1024
    g_W1T[1024 * E_DIM + idx] = Wk[idx];
    g_W1T[1088 * E_DIM + idx] = Wv[idx];
}

// ---------------- prep 3 ----------------
__global__ __launch_bounds__(256) void prep_w2_kernel(const float* __restrict__ vup,
                                                      const float* __restrict__ Wout) {
    __shared__ __align__(16) float Wos[64][68];
    __shared__ __align__(16) float Vus[64][68];
    const int h  = blockIdx.y;
    const int e0 = blockIdx.x * 64;
    const int tid = threadIdx.x, tx = tid & 15, ty = tid >> 4;

    #pragma unroll
    for (int i = 0; i < 16; i++) {
        int lin = tid + i * 256;
        int c = lin & 63, r = lin >> 6;
        Wos[r][c] = Wout[(e0 + r) * E_DIM + h * 64 + c];
        Vus[r][c] = vup[(h * 64 + r) * 64 + c];
    }
    __syncthreads();

    float acc[4][4];
    #pragma unroll
    for (int i = 0; i < 4; i++)
        #pragma unroll
        for (int j = 0; j < 4; j++) acc[i][j] = 0.f;

    #pragma unroll
    for (int d4 = 0; d4 < 16; d4++) {
        float4 a[4], b[4];
        #pragma unroll
        for (int i = 0; i < 4; i++) a[i] = *(const float4*)&Vus[ty * 4 + i][d4 * 4];
        #pragma unroll
        for (int j = 0; j < 4; j++) b[j] = *(const float4*)&Wos[tx * 4 + j][d4 * 4];
        #pragma unroll
        for (int i = 0; i < 4; i++)
            #pragma unroll
            for (int j = 0; j < 4; j++)
                acc[i][j] += a[i].x * b[j].x + a[i].y * b[j].y +
                             a[i].z * b[j].z + a[i].w * b[j].w;
    }
    #pragma unroll
    for (int j = 0; j < 4; j++)
        #pragma unroll
        for (int i = 0; i < 4; i++)
            g_W2T[(e0 + tx * 4 + j) * E_DIM + h * 64 + ty * 4 + i] = acc[i][j];
}

// ==================== 3xTF32 mma.sync GEMM, cp.async double-buffered ====================
// C[M,N] = A[M,K] @ BT[N,K]^T.  CTA 128x128, 256 threads (8 warps: 4m x 2n).
// smem: raw fp32, 2 stages x { A[128][36], B[128][36] }.  tf32 split in registers.
#define GPAD 36
#define GST  (2 * 128 * GPAD)            // words per stage (A + B)
#define GB_OFF (128 * GPAD)              // B offset inside a stage
#define GEMM_SMEM (2 * GST * 4)

__global__ __launch_bounds__(256) void gemm_mma(const float* __restrict__ A,
                                                const float* __restrict__ BT,
                                                float* __restrict__ C,
                                                int N, int K) {
    extern __shared__ uint32_t gsm[];
    const float* gsmF = (const float*)gsm;
    const uint32_t sbase = smem_u32(gsm);

    const int tid = threadIdx.x;
    const int wid = tid >> 5, lane = tid & 31;
    const int g = lane >> 2, tig = lane & 3;
    const int wm = wid & 3, wn = wid >> 2;
    const int m0 = blockIdx.y * 128;
    const int n0 = blockIdx.x * 128;
    const int nst = K >> 5;

    // per-thread fetch coordinates: 4 A chunks + 4 B chunks (1024 chunks each)
    const int frow[4] = { (tid + 0) >> 3, (tid + 256) >> 3, (tid + 512) >> 3, (tid + 768) >> 3 };
    const int fcol = (tid & 7) * 4;

    float c[2][8][4];
    #pragma unroll
    for (int mt = 0; mt < 2; mt++)
        #pragma unroll
        for (int nt = 0; nt < 8; nt++)
            #pragma unroll
            for (int j = 0; j < 4; j++) c[mt][nt][j] = 0.f;

    // prologue fetch stage 0
    {
        #pragma unroll
        for (int i = 0; i < 4; i++) {
            int row = frow[i];
            uint32_t da = sbase + (uint32_t)(row * GPAD + fcol) * 4u;
            uint32_t db = sbase + (uint32_t)(GB_OFF + row * GPAD + fcol) * 4u;
            cp_async16(da, &A[(size_t)(m0 + row) * K + fcol]);
            cp_async16(db, &BT[(size_t)(n0 + row) * K + fcol]);
        }
        CP_COMMIT();
    }

    for (int s = 0; s < nst; s++) {
        const int buf = s & 1;
        if (s + 1 < nst) {
            const int nb = (s + 1) & 1;
            const int k0 = (s + 1) << 5;
            #pragma unroll
            for (int i = 0; i < 4; i++) {
                int row = frow[i];
                uint32_t da = sbase + (uint32_t)(nb * GST + row * GPAD + fcol) * 4u;
                uint32_t db = sbase + (uint32_t)(nb * GST + GB_OFF + row * GPAD + fcol) * 4u;
                cp_async16(da, &A[(size_t)(m0 + row) * K + k0 + fcol]);
                cp_async16(db, &BT[(size_t)(n0 + row) * K + k0 + fcol]);
            }
            CP_COMMIT();
            CP_WAIT(1);
        } else {
            CP_WAIT(0);
        }
        __syncthreads();

        const int ab = buf * GST;
        const int bb = buf * GST + GB_OFF;
        #pragma unroll
        for (int ks = 0; ks < 4; ks++) {
            uint32_t ah[2][4], al[2][4];
            #pragma unroll
            for (int mt = 0; mt < 2; mt++) {
                int r0 = ab + (wm * 32 + mt * 16 + g) * GPAD + ks * 8 + tig;
                int r1 = ab + (wm * 32 + mt * 16 + g + 8) * GPAD + ks * 8 + tig;
                tf32_split(gsmF[r0],     ah[mt][0], al[mt][0]);
                tf32_split(gsmF[r1],     ah[mt][1], al[mt][1]);
                tf32_split(gsmF[r0 + 4], ah[mt][2], al[mt][2]);
                tf32_split(gsmF[r1 + 4], ah[mt][3], al[mt][3]);
            }
            #pragma unroll
            for (int nt = 0; nt < 8; nt++) {
                int rb = bb + (wn * 64 + nt * 8 + g) * GPAD + ks * 8 + tig;
                uint32_t bh0, bl0, bh1, bl1;
                tf32_split(gsmF[rb],     bh0, bl0);
                tf32_split(gsmF[rb + 4], bh1, bl1);
                #pragma unroll
                for (int mt = 0; mt < 2; mt++) {
                    mma_tf32(c[mt][nt], ah[mt], bh0, bh1);
                    mma_tf32(c[mt][nt], ah[mt], bl0, bl1);
                    mma_tf32(c[mt][nt], al[mt], bh0, bh1);
                }
            }
        }
        __syncthreads();
    }

    // epilogue
    #pragma unroll
    for (int mt = 0; mt < 2; mt++) {
        int row0 = m0 + wm * 32 + mt * 16 + g;
        #pragma unroll
        for (int nt = 0; nt < 8; nt++) {
            int col = n0 + wn * 64 + nt * 8 + 2 * tig;
            *(float2*)&C[(size_t)row0 * N + col]       = make_float2(c[mt][nt][0], c[mt][nt][1]);
            *(float2*)&C[(size_t)(row0 + 8) * N + col] = make_float2(c[mt][nt][2], c[mt][nt][3]);
        }
    }
}

// ==================== tf32 mma.sync flash attention, cp.async KV double-buffer ========
// CTA: 128-query tile, 8 warps x 16 rows.  KV tiles of 64, latent dim L=64.
// smem words: Qs[128][68] tf32 | 2 x { K[64][68] raw fp32, V[64][72] raw fp32 } | P[8][16][68]
#define QS_OFF 0
#define KV_OFF (128 * 68)
#define KV_ST  (64 * 68 + 64 * 72)       // 8960 words per stage
#define KV_VOFF (64 * 68)
#define PS_OFF (KV_OFF + 2 * KV_ST)
#define ATTN_SMEM ((PS_OFF + 8 * 16 * 68) * 4)

__global__ __launch_bounds__(256, 1) void attn_mma() {
    extern __shared__ uint32_t sm[];
    const uint32_t sbase = smem_u32(sm);
    const int tid = threadIdx.x;
    const int wid = tid >> 5, lane = tid & 31;
    const int g = lane >> 2, tig = lane & 3;
    const int wq = wid * 16;
    const int qt = (int)gridDim.x - 1 - (int)blockIdx.x;  // heavy first
    const int h  = blockIdx.y;
    const int q0 = qt * 128;
    const int nkv = 2 * qt + 2;

    // per-thread KV fetch coords: 64 rows x 16 chunks = 1024 chunks each of K and V
    const int kr[4] = { (tid + 0) >> 4, (tid + 256) >> 4, (tid + 512) >> 4, (tid + 768) >> 4 };
    const int kc = (tid & 15) * 4;

    // prologue: fetch KV block 0 into stage 0
    {
        #pragma unroll
        for (int i = 0; i < 4; i++) {
            int r = kr[i];
            const float* src = &g_mid[(size_t)r * NMID + 1024 + kc];
            cp_async16(sbase + (uint32_t)(KV_OFF + r * 68 + kc) * 4u, src);
            cp_async16(sbase + (uint32_t)(KV_OFF + KV_VOFF + r * 72 + kc) * 4u, src + 64);
        }
        CP_COMMIT();
    }

    // stage Q (scaled by 1/sqrt(L)=0.125, tf32-rounded)
    #pragma unroll
    for (int i = 0; i < 8; i++) {
        int lin = tid + i * 256;                  // 2048 float4 slots
        int r = lin >> 4, c4 = lin & 15;
        float4 v = *(const float4*)&g_mid[(size_t)(q0 + r) * NMID + h * 64 + c4 * 4];
        uint32_t* dst = &sm[QS_OFF + r * 68 + c4 * 4];
        dst[0] = f2tf32(v.x * 0.125f); dst[1] = f2tf32(v.y * 0.125f);
        dst[2] = f2tf32(v.z * 0.125f); dst[3] = f2tf32(v.w * 0.125f);
    }
    __syncthreads();

    // preload Q A-fragments
    uint32_t qa[8][4];
    #pragma unroll
    for (int ks = 0; ks < 8; ks++) {
        int r0 = (wq + g) * 68 + ks * 8 + tig;
        int r1 = (wq + g + 8) * 68 + ks * 8 + tig;
        qa[ks][0] = sm[QS_OFF + r0]; qa[ks][1] = sm[QS_OFF + r1];
        qa[ks][2] = sm[QS_OFF + r0 + 4]; qa[ks][3] = sm[QS_OFF + r1 + 4];
    }

    float o[8][4];
    #pragma unroll
    for (int nt = 0; nt < 8; nt++)
        #pragma unroll
        for (int j = 0; j < 4; j++) o[nt][j] = 0.f;
    float m0r = -1e30f, m1r = -1e30f, l0r = 0.f, l1r = 0.f;

    uint32_t* Pw = &sm[PS_OFF + wid * 16 * 68];

    for (int kb = 0; kb < nkv; kb++) {
        const int buf = kb & 1;
        if (kb + 1 < nkv) {
            const int nb = (kb + 1) & 1;
            const int ns0 = (kb + 1) * 64;
            #pragma unroll
            for (int i = 0; i < 4; i++) {
                int r = kr[i];
                const float* src = &g_mid[(size_t)(ns0 + r) * NMID + 1024 + kc];
                cp_async16(sbase + (uint32_t)(KV_OFF + nb * KV_ST + r * 68 + kc) * 4u, src);
                cp_async16(sbase + (uint32_t)(KV_OFF + nb * KV_ST + KV_VOFF + r * 72 + kc) * 4u, src + 64);
            }
            CP_COMMIT();
            CP_WAIT(1);
        } else {
            CP_WAIT(0);
        }
        __syncthreads();

        const uint32_t* Kb = &sm[KV_OFF + buf * KV_ST];
        const uint32_t* Vb = &sm[KV_OFF + buf * KV_ST + KV_VOFF];
        const int s0 = kb * 64;

        // S = Q @ K^T   (K raw fp32 bits; tf32 truncation in HW)
        float s[8][4];
        #pragma unroll
        for (int nt = 0; nt < 8; nt++) {
            s[nt][0] = s[nt][1] = s[nt][2] = s[nt][3] = 0.f;
            #pragma unroll
            for (int ks = 0; ks < 8; ks++) {
                int rb = (nt * 8 + g) * 68 + ks * 8 + tig;
                mma_tf32(s[nt], qa[ks], Kb[rb], Kb[rb + 4]);
            }
        }

        // causal mask (only on last two tiles of this q block)
        if (kb >= 2 * qt) {
            int row0 = q0 + wq + g, row1 = row0 + 8;
            #pragma unroll
            for (int nt = 0; nt < 8; nt++) {
                int c0 = s0 + nt * 8 + 2 * tig;
                if (c0     > row0) s[nt][0] = -1e30f;
                if (c0 + 1 > row0) s[nt][1] = -1e30f;
                if (c0     > row1) s[nt][2] = -1e30f;
                if (c0 + 1 > row1) s[nt][3] = -1e30f;
            }
        }

        // online softmax
        float rm0 = -1e30f, rm1 = -1e30f;
        #pragma unroll
        for (int nt = 0; nt < 8; nt++) {
            rm0 = fmaxf(rm0, fmaxf(s[nt][0], s[nt][1]));
            rm1 = fmaxf(rm1, fmaxf(s[nt][2], s[nt][3]));
        }
        rm0 = fmaxf(rm0, __shfl_xor_sync(0xffffffffu, rm0, 1));
        rm0 = fmaxf(rm0, __shfl_xor_sync(0xffffffffu, rm0, 2));
        rm1 = fmaxf(rm1, __shfl_xor_sync(0xffffffffu, rm1, 1));
        rm1 = fmaxf(rm1, __shfl_xor_sync(0xffffffffu, rm1, 2));
        float mn0 = fmaxf(m0r, rm0), mn1 = fmaxf(m1r, rm1);
        float al0 = __expf(m0r - mn0), al1 = __expf(m1r - mn1);
        m0r = mn0; m1r = mn1;

        float rs0 = 0.f, rs1 = 0.f;
        #pragma unroll
        for (int nt = 0; nt < 8; nt++) {
            s[nt][0] = __expf(s[nt][0] - mn0); rs0 += s[nt][0];
            s[nt][1] = __expf(s[nt][1] - mn0); rs0 += s[nt][1];
            s[nt][2] = __expf(s[nt][2] - mn1); rs1 += s[nt][2];
            s[nt][3] = __expf(s[nt][3] - mn1); rs1 += s[nt][3];
        }
        rs0 += __shfl_xor_sync(0xffffffffu, rs0, 1);
        rs0 += __shfl_xor_sync(0xffffffffu, rs0, 2);
        rs1 += __shfl_xor_sync(0xffffffffu, rs1, 1);
        rs1 += __shfl_xor_sync(0xffffffffu, rs1, 2);
        l0r = l0r * al0 + rs0;
        l1r = l1r * al1 + rs1;

        // stage P (tf32 bits) into per-warp region
        #pragma unroll
        for (int nt = 0; nt < 8; nt++) {
            int cc = nt * 8 + 2 * tig;
            Pw[g * 68 + cc]           = f2tf32(s[nt][0]);
            Pw[g * 68 + cc + 1]       = f2tf32(s[nt][1]);
            Pw[(g + 8) * 68 + cc]     = f2tf32(s[nt][2]);
            Pw[(g + 8) * 68 + cc + 1] = f2tf32(s[nt][3]);
        }
        __syncwarp();

        // O = O*alpha + P @ V   (V raw fp32 bits)
        #pragma unroll
        for (int nt = 0; nt < 8; nt++) {
            o[nt][0] *= al0; o[nt][1] *= al0;
            o[nt][2] *= al1; o[nt][3] *= al1;
        }
        #pragma unroll
        for (int ks = 0; ks < 8; ks++) {
            uint32_t pa[4];
            int kcc = ks * 8 + tig;
            pa[0] = Pw[g * 68 + kcc];     pa[1] = Pw[(g + 8) * 68 + kcc];
            pa[2] = Pw[g * 68 + kcc + 4]; pa[3] = Pw[(g + 8) * 68 + kcc + 4];
            #pragma unroll
            for (int nt = 0; nt < 8; nt++) {
                uint32_t v0 = Vb[(ks * 8 + tig) * 72 + nt * 8 + g];
                uint32_t v1 = Vb[(ks * 8 + tig + 4) * 72 + nt * 8 + g];
                mma_tf32(o[nt], pa, v0, v1);
            }
        }
        __syncthreads();
    }

    // normalize + write ctx
    float inv0 = 1.0f / l0r, inv1 = 1.0f / l1r;
    int row0 = q0 + wq + g;
    #pragma unroll
    for (int nt = 0; nt < 8; nt++) {
        int col = h * 64 + nt * 8 + 2 * tig;
        *(float2*)&g_ctx[(size_t)row0 * E_DIM + col] =
            make_float2(o[nt][0] * inv0, o[nt][1] * inv0);
        *(float2*)&g_ctx[(size_t)(row0 + 8) * E_DIM + col] =
            make_float2(o[nt][2] * inv1, o[nt][3] * inv1);
    }
}

// ---------------- launch ----------------
extern "C" void kernel_launch(void* const* d_in, const int* in_sizes, int n_in,
                              void* d_out, int out_size) {
    const float* hidden = (const float*)d_in[0];
    const float* Wq     = (const float*)d_in[1];
    const float* Wk     = (const float*)d_in[2];
    const float* Wv     = (const float*)d_in[3];
    const float* q2l    = (const float*)d_in[4];
    const float* vup    = (const float*)d_in[5];
    const float* Wout   = (const float*)d_in[6];
    float* out = (float*)d_out;

    void *w1p, *w2p, *midp, *ctxp;
    cudaGetSymbolAddress(&w1p,  g_W1T);
    cudaGetSymbolAddress(&w2p,  g_W2T);
    cudaGetSymbolAddress(&midp, g_mid);
    cudaGetSymbolAddress(&ctxp, g_ctx);

    cudaFuncSetAttribute(gemm_mma, cudaFuncAttributeMaxDynamicSharedMemorySize, GEMM_SMEM);
    cudaFuncSetAttribute(attn_mma, cudaFuncAttributeMaxDynamicSharedMemorySize, ATTN_SMEM);

    // weight fusion preps (emit B transposed: [N][K] K-major)
    prep_w1_kernel<<<dim3(16, 16), 256>>>(Wq, q2l);
    prep_kv_kernel<<<256, 256>>>(Wk, Wv);
    prep_w2_kernel<<<dim3(16, 16), 256>>>(vup, Wout);

    // mid = hidden @ W1   (2048 x 1152 x 1024), 3xTF32 mma.sync
    gemm_mma<<<dim3(NMID / 128, T_SEQ / 128), 256, GEMM_SMEM>>>(
        hidden, (const float*)w1p, (float*)midp, NMID, E_DIM);

    // flash attention over latent K/V, tf32 mma.sync
    attn_mma<<<dim3(T_SEQ / 128, H_NUM), 256, ATTN_SMEM>>>();

    // out = ctx @ W2   (2048 x 1024 x 1024), 3xTF32 mma.sync
    gemm_mma<<<dim3(E_DIM / 128, T_SEQ / 128), 256, GEMM_SMEM>>>(
        (const float*)ctxp, (const float*)w2p, out, E_DIM, E_DIM);
}

// round 7
// speedup vs baseline: 2.4913x; 1.0172x over previous
#include <cuda_runtime.h>
#include <cstdint>

#define T_SEQ 2048
#define E_DIM 1024
#define H_NUM 16
#define L_DIM 64
#define NMID  1152   // 1024 q_lat cols + 64 latent_k + 64 latent_v

// ==================== helpers ====================
__device__ __forceinline__ uint32_t f2tf32(float x) {
    uint32_t b;
    asm("cvt.rna.tf32.f32 %0, %1;" : "=r"(b) : "f"(x));
    return b;
}

// D(16x8,fp32) += A(16x8,tf32) * B(8x8,tf32)
__device__ __forceinline__ void mma_tf32(float* c, const uint32_t* a, uint32_t b0, uint32_t b1) {
    asm volatile(
        "mma.sync.aligned.m16n8k8.row.col.f32.tf32.tf32.f32 "
        "{%0,%1,%2,%3}, {%4,%5,%6,%7}, {%8,%9}, {%0,%1,%2,%3};"
        : "+f"(c[0]), "+f"(c[1]), "+f"(c[2]), "+f"(c[3])
        : "r"(a[0]), "r"(a[1]), "r"(a[2]), "r"(a[3]), "r"(b0), "r"(b1));
}

__device__ __forceinline__ uint32_t smem_u32(const void* p) {
    uint32_t a;
    asm("{ .reg .u64 t; cvta.to.shared.u64 t, %1; cvt.u32.u64 %0, t; }" : "=r"(a) : "l"(p));
    return a;
}

__device__ __forceinline__ void cp_async16(uint32_t dst, const void* src) {
    asm volatile("cp.async.cg.shared.global [%0], [%1], 16;" :: "r"(dst), "l"(src));
}
#define CP_COMMIT()  asm volatile("cp.async.commit_group;" ::: "memory")
#define CP_WAIT(N)   asm volatile("cp.async.wait_group %0;" :: "n"(N) : "memory")

__device__ __forceinline__ void split2(float v, float& hf, float& lf) {
    hf = __uint_as_float(f2tf32(v));
    lf = __uint_as_float(f2tf32(v - hf));
}

// ==================== device scratch ====================
__device__ float g_W1Th[NMID * E_DIM], g_W1Tl[NMID * E_DIM];
__device__ float g_W2Th[E_DIM * E_DIM], g_W2Tl[E_DIM * E_DIM];
__device__ float g_Ah[T_SEQ * E_DIM],  g_Al[T_SEQ * E_DIM];   // split A (hidden, then ctx)
__device__ float g_mid[T_SEQ * NMID];    // [q_lat*0.125 | latent_k | latent_v], tf32-rounded
__device__ float g_ctx[T_SEQ * E_DIM];   // ctx_lat flattened [t, h*64+l], fp32

// ---------------- split A: hi/lo tf32 decomposition ----------------
__global__ __launch_bounds__(256) void split_kernel(const float* __restrict__ src,
                                                    float* __restrict__ hi,
                                                    float* __restrict__ lo) {
    int i = (blockIdx.x * 256 + threadIdx.x) * 4;
    float4 v = *(const float4*)&src[i];
    float4 h, l;
    split2(v.x, h.x, l.x); split2(v.y, h.y, l.y);
    split2(v.z, h.z, l.z); split2(v.w, h.w, l.w);
    *(float4*)&hi[i] = h;
    *(float4*)&lo[i] = l;
}

// ---------------- prep 1: W1T[h*64+l][e] = sum_d Wq[h*64+d, e] * q2l[h,d,l] ----
__global__ __launch_bounds__(256) void prep_w1_kernel(const float* __restrict__ Wq,
                                                      const float* __restrict__ q2l) {
    __shared__ float Wqs[64][65];
    __shared__ float Qls[64][65];
    const int h  = blockIdx.y;
    const int e0 = blockIdx.x * 64;
    const int tid = threadIdx.x, tx = tid & 15, ty = tid >> 4;

    #pragma unroll
    for (int i = 0; i < 16; i++) {
        int lin = tid + i * 256;
        int c = lin & 63, r = lin >> 6;
        Wqs[r][c] = Wq[(h * 64 + r) * E_DIM + e0 + c];
        Qls[r][c] = q2l[(h * 64 + r) * 64 + c];
    }
    __syncthreads();

    float acc[4][4];
    #pragma unroll
    for (int i = 0; i < 4; i++)
        #pragma unroll
        for (int j = 0; j < 4; j++) acc[i][j] = 0.f;

    #pragma unroll 8
    for (int d = 0; d < 64; d++) {
        float a[4], b[4];
        #pragma unroll
        for (int i = 0; i < 4; i++) a[i] = Wqs[d][ty * 4 + i];
        #pragma unroll
        for (int j = 0; j < 4; j++) b[j] = Qls[d][tx * 4 + j];
        #pragma unroll
        for (int i = 0; i < 4; i++)
            #pragma unroll
            for (int j = 0; j < 4; j++) acc[i][j] += a[i] * b[j];
    }
    #pragma unroll
    for (int j = 0; j < 4; j++)
        #pragma unroll
        for (int i = 0; i < 4; i++) {
            int idx = (h * 64 + tx * 4 + j) * E_DIM + e0 + ty * 4 + i;
            float hf, lf; split2(acc[i][j], hf, lf);
            g_W1Th[idx] = hf; g_W1Tl[idx] = lf;
        }
}

// ---------------- prep 2: W1T rows 1024+l / 1088+l are Wk_down / Wv_down ----
__global__ __launch_bounds__(256) void prep_kv_kernel(const float* __restrict__ Wk,
                                                      const float* __restrict__ Wv) {
    int idx = blockIdx.x * 256 + threadIdx.x;   // 64 * 1024
    float hf, lf;
    split2(Wk[idx], hf, lf);
    g_W1Th[1024 * E_DIM + idx] = hf; g_W1Tl[1024 * E_DIM + idx] = lf;
    split2(Wv[idx], hf, lf);
    g_W1Th[1088 * E_DIM + idx] = hf; g_W1Tl[1088 * E_DIM + idx] = lf;
}

// ---------------- prep 3: W2T[e][h*64+l] = sum_d v_up[h,l,d] * Wout[e, h*64+d] ----
__global__ __launch_bounds__(256) void prep_w2_kernel(const float* __restrict__ vup,
                                                      const float* __restrict__ Wout) {
    __shared__ __align__(16) float Wos[64][68];
    __shared__ __align__(16) float Vus[64][68];
    const int h  = blockIdx.y;
    const int e0 = blockIdx.x * 64;
    const int tid = threadIdx.x, tx = tid & 15, ty = tid >> 4;

    #pragma unroll
    for (int i = 0; i < 16; i++) {
        int lin = tid + i * 256;
        int c = lin & 63, r = lin >> 6;
        Wos[r][c] = Wout[(e0 + r) * E_DIM + h * 64 + c];
        Vus[r][c] = vup[(h * 64 + r) * 64 + c];
    }
    __syncthreads();

    float acc[4][4];
    #pragma unroll
    for (int i = 0; i < 4; i++)
        #pragma unroll
        for (int j = 0; j < 4; j++) acc[i][j] = 0.f;

    #pragma unroll
    for (int d4 = 0; d4 < 16; d4++) {
        float4 a[4], b[4];
        #pragma unroll
        for (int i = 0; i < 4; i++) a[i] = *(const float4*)&Vus[ty * 4 + i][d4 * 4];
        #pragma unroll
        for (int j = 0; j < 4; j++) b[j] = *(const float4*)&Wos[tx * 4 + j][d4 * 4];
        #pragma unroll
        for (int i = 0; i < 4; i++)
            #pragma unroll
            for (int j = 0; j < 4; j++)
                acc[i][j] += a[i].x * b[j].x + a[i].y * b[j].y +
                             a[i].z * b[j].z + a[i].w * b[j].w;
    }
    #pragma unroll
    for (int j = 0; j < 4; j++)
        #pragma unroll
        for (int i = 0; i < 4; i++) {
            int idx = (e0 + tx * 4 + j) * E_DIM + h * 64 + ty * 4 + i;
            float hf, lf; split2(acc[i][j], hf, lf);
            g_W2Th[idx] = hf; g_W2Tl[idx] = lf;
        }
}

// ==================== 3xTF32 mma.sync GEMM, pre-split operands, cp.async x2 ==========
// C[M,N] = A[M,K] @ BT[N,K]^T with A = Ah+Al, BT = Bh+Bl (tf32 values).
// CTA 128x128, 256 threads (8 warps: 4m x 2n).  2 stages x 4 tiles [128][36].
#define GPAD 36
#define TILE_W (128 * GPAD)              // words per tile
#define GST  (4 * TILE_W)                // words per stage (Ah,Al,Bh,Bl)
#define GEMM_SMEM (2 * GST * 4)

__global__ __launch_bounds__(256) void gemm_mma(const float* __restrict__ Ah,
                                                const float* __restrict__ Al,
                                                const float* __restrict__ Bh,
                                                const float* __restrict__ Bl,
                                                float* __restrict__ C,
                                                int N, int K, int mode) {
    extern __shared__ uint32_t gsm[];
    const uint32_t sbase = smem_u32(gsm);

    const int tid = threadIdx.x;
    const int wid = tid >> 5, lane = tid & 31;
    const int g = lane >> 2, tig = lane & 3;
    const int wm = wid & 3, wn = wid >> 2;
    const int m0 = blockIdx.y * 128;
    const int n0 = blockIdx.x * 128;
    const int nst = K >> 5;

    const int frow[4] = { (tid + 0) >> 3, (tid + 256) >> 3, (tid + 512) >> 3, (tid + 768) >> 3 };
    const int fcol = (tid & 7) * 4;

    float c[2][8][4];
    #pragma unroll
    for (int mt = 0; mt < 2; mt++)
        #pragma unroll
        for (int nt = 0; nt < 8; nt++)
            #pragma unroll
            for (int j = 0; j < 4; j++) c[mt][nt][j] = 0.f;

    // fetch one stage (k0 = stage*32) into buffer b
    auto fetch = [&](int k0, int b) {
        const uint32_t s0 = sbase + (uint32_t)(b * GST) * 4u;
        #pragma unroll
        for (int i = 0; i < 4; i++) {
            int row = frow[i];
            uint32_t off = (uint32_t)(row * GPAD + fcol) * 4u;
            size_t ga = (size_t)(m0 + row) * K + k0 + fcol;
            size_t gb = (size_t)(n0 + row) * K + k0 + fcol;
            cp_async16(s0 + 0 * TILE_W * 4 + off, &Ah[ga]);
            cp_async16(s0 + 1 * TILE_W * 4 + off, &Al[ga]);
            cp_async16(s0 + 2 * TILE_W * 4 + off, &Bh[gb]);
            cp_async16(s0 + 3 * TILE_W * 4 + off, &Bl[gb]);
        }
        CP_COMMIT();
    };

    fetch(0, 0);

    for (int s = 0; s < nst; s++) {
        const int buf = s & 1;
        if (s + 1 < nst) { fetch((s + 1) << 5, buf ^ 1); CP_WAIT(1); }
        else             { CP_WAIT(0); }
        __syncthreads();

        const int ah0 = buf * GST;
        const int al0 = ah0 + TILE_W;
        const int bh0 = ah0 + 2 * TILE_W;
        const int bl0 = ah0 + 3 * TILE_W;
        #pragma unroll
        for (int ks = 0; ks < 4; ks++) {
            uint32_t ah[2][4], al[2][4];
            #pragma unroll
            for (int mt = 0; mt < 2; mt++) {
                int r0 = (wm * 32 + mt * 16 + g) * GPAD + ks * 8 + tig;
                int r1 = (wm * 32 + mt * 16 + g + 8) * GPAD + ks * 8 + tig;
                ah[mt][0] = gsm[ah0 + r0]; ah[mt][1] = gsm[ah0 + r1];
                ah[mt][2] = gsm[ah0 + r0 + 4]; ah[mt][3] = gsm[ah0 + r1 + 4];
                al[mt][0] = gsm[al0 + r0]; al[mt][1] = gsm[al0 + r1];
                al[mt][2] = gsm[al0 + r0 + 4]; al[mt][3] = gsm[al0 + r1 + 4];
            }
            #pragma unroll
            for (int nt = 0; nt < 8; nt++) {
                int rb = (wn * 64 + nt * 8 + g) * GPAD + ks * 8 + tig;
                uint32_t h0 = gsm[bh0 + rb], h1 = gsm[bh0 + rb + 4];
                uint32_t l0 = gsm[bl0 + rb], l1 = gsm[bl0 + rb + 4];
                #pragma unroll
                for (int mt = 0; mt < 2; mt++) {
                    mma_tf32(c[mt][nt], ah[mt], h0, h1);
                    mma_tf32(c[mt][nt], ah[mt], l0, l1);
                    mma_tf32(c[mt][nt], al[mt], h0, h1);
                }
            }
        }
        __syncthreads();
    }

    // epilogue: mode 1 = GEMM1 (round to tf32; scale q_lat cols by 0.125)
    #pragma unroll
    for (int mt = 0; mt < 2; mt++) {
        int row0 = m0 + wm * 32 + mt * 16 + g;
        #pragma unroll
        for (int nt = 0; nt < 8; nt++) {
            int col = n0 + wn * 64 + nt * 8 + 2 * tig;
            float v0 = c[mt][nt][0], v1 = c[mt][nt][1];
            float v2 = c[mt][nt][2], v3 = c[mt][nt][3];
            if (mode == 1) {
                float sc = (col < 1024) ? 0.125f : 1.0f;   // col,col+1 same side (1024%8==0)
                v0 = __uint_as_float(f2tf32(v0 * sc));
                v1 = __uint_as_float(f2tf32(v1 * sc));
                v2 = __uint_as_float(f2tf32(v2 * sc));
                v3 = __uint_as_float(f2tf32(v3 * sc));
            }
            *(float2*)&C[(size_t)row0 * N + col]       = make_float2(v0, v1);
            *(float2*)&C[(size_t)(row0 + 8) * N + col] = make_float2(v2, v3);
        }
    }
}

// ==================== tf32 mma.sync flash attention, all-cp.async ====================
// CTA: 128-query tile, 8 warps x 16 rows.  KV tiles of 64, latent dim L=64.
// All of Q/K/V already tf32-rounded in g_mid (GEMM1 epilogue) -> raw-bit fragments.
#define QS_OFF 0
#define KV_OFF (128 * 68)
#define KV_ST  (64 * 68 + 64 * 72)       // words per stage
#define KV_VOFF (64 * 68)
#define PS_OFF (KV_OFF + 2 * KV_ST)
#define ATTN_SMEM ((PS_OFF + 8 * 16 * 68) * 4)

__global__ __launch_bounds__(256, 1) void attn_mma() {
    extern __shared__ uint32_t sm[];
    const uint32_t sbase = smem_u32(sm);
    const int tid = threadIdx.x;
    const int wid = tid >> 5, lane = tid & 31;
    const int g = lane >> 2, tig = lane & 3;
    const int wq = wid * 16;
    const int qt = (int)gridDim.x - 1 - (int)blockIdx.x;  // heavy first
    const int h  = blockIdx.y;
    const int q0 = qt * 128;
    const int nkv = 2 * qt + 2;

    const int kr[4] = { (tid + 0) >> 4, (tid + 256) >> 4, (tid + 512) >> 4, (tid + 768) >> 4 };
    const int kc = (tid & 15) * 4;

    auto fetch_kv = [&](int blk, int b) {
        #pragma unroll
        for (int i = 0; i < 4; i++) {
            int r = kr[i];
            const float* src = &g_mid[(size_t)(blk * 64 + r) * NMID + 1024 + kc];
            cp_async16(sbase + (uint32_t)(KV_OFF + b * KV_ST + r * 68 + kc) * 4u, src);
            cp_async16(sbase + (uint32_t)(KV_OFF + b * KV_ST + KV_VOFF + r * 72 + kc) * 4u, src + 64);
        }
        CP_COMMIT();
    };

    // prologue: KV block 0 (group), Q tile (group), wait for both
    fetch_kv(0, 0);
    {
        #pragma unroll
        for (int i = 0; i < 8; i++) {
            int lin = tid + i * 256;                  // 2048 16B chunks
            int r = lin >> 4, c4 = lin & 15;
            cp_async16(sbase + (uint32_t)(QS_OFF + r * 68 + c4 * 4) * 4u,
                       &g_mid[(size_t)(q0 + r) * NMID + h * 64 + c4 * 4]);
        }
        CP_COMMIT();
    }
    CP_WAIT(0);
    __syncthreads();

    // preload Q A-fragments (already tf32 bits)
    uint32_t qa[8][4];
    #pragma unroll
    for (int ks = 0; ks < 8; ks++) {
        int r0 = (wq + g) * 68 + ks * 8 + tig;
        int r1 = (wq + g + 8) * 68 + ks * 8 + tig;
        qa[ks][0] = sm[QS_OFF + r0]; qa[ks][1] = sm[QS_OFF + r1];
        qa[ks][2] = sm[QS_OFF + r0 + 4]; qa[ks][3] = sm[QS_OFF + r1 + 4];
    }

    float o[8][4];
    #pragma unroll
    for (int nt = 0; nt < 8; nt++)
        #pragma unroll
        for (int j = 0; j < 4; j++) o[nt][j] = 0.f;
    float m0r = -1e30f, m1r = -1e30f, l0r = 0.f, l1r = 0.f;

    uint32_t* Pw = &sm[PS_OFF + wid * 16 * 68];

    for (int kb = 0; kb < nkv; kb++) {
        const int buf = kb & 1;
        if (kb + 1 < nkv) { fetch_kv(kb + 1, buf ^ 1); CP_WAIT(1); }
        else              { CP_WAIT(0); }
        __syncthreads();

        const uint32_t* Kb = &sm[KV_OFF + buf * KV_ST];
        const uint32_t* Vb = &sm[KV_OFF + buf * KV_ST + KV_VOFF];
        const int s0 = kb * 64;

        // S = Q @ K^T
        float s[8][4];
        #pragma unroll
        for (int nt = 0; nt < 8; nt++) {
            s[nt][0] = s[nt][1] = s[nt][2] = s[nt][3] = 0.f;
            #pragma unroll
            for (int ks = 0; ks < 8; ks++) {
                int rb = (nt * 8 + g) * 68 + ks * 8 + tig;
                mma_tf32(s[nt], qa[ks], Kb[rb], Kb[rb + 4]);
            }
        }

        // causal mask (only on last two tiles of this q block)
        if (kb >= 2 * qt) {
            int row0 = q0 + wq + g, row1 = row0 + 8;
            #pragma unroll
            for (int nt = 0; nt < 8; nt++) {
                int c0 = s0 + nt * 8 + 2 * tig;
                if (c0     > row0) s[nt][0] = -1e30f;
                if (c0 + 1 > row0) s[nt][1] = -1e30f;
                if (c0     > row1) s[nt][2] = -1e30f;
                if (c0 + 1 > row1) s[nt][3] = -1e30f;
            }
        }

        // online softmax
        float rm0 = -1e30f, rm1 = -1e30f;
        #pragma unroll
        for (int nt = 0; nt < 8; nt++) {
            rm0 = fmaxf(rm0, fmaxf(s[nt][0], s[nt][1]));
            rm1 = fmaxf(rm1, fmaxf(s[nt][2], s[nt][3]));
        }
        rm0 = fmaxf(rm0, __shfl_xor_sync(0xffffffffu, rm0, 1));
        rm0 = fmaxf(rm0, __shfl_xor_sync(0xffffffffu, rm0, 2));
        rm1 = fmaxf(rm1, __shfl_xor_sync(0xffffffffu, rm1, 1));
        rm1 = fmaxf(rm1, __shfl_xor_sync(0xffffffffu, rm1, 2));
        float mn0 = fmaxf(m0r, rm0), mn1 = fmaxf(m1r, rm1);
        float al0 = __expf(m0r - mn0), al1 = __expf(m1r - mn1);
        m0r = mn0; m1r = mn1;

        float rs0 = 0.f, rs1 = 0.f;
        #pragma unroll
        for (int nt = 0; nt < 8; nt++) {
            s[nt][0] = __expf(s[nt][0] - mn0); rs0 += s[nt][0];
            s[nt][1] = __expf(s[nt][1] - mn0); rs0 += s[nt][1];
            s[nt][2] = __expf(s[nt][2] - mn1); rs1 += s[nt][2];
            s[nt][3] = __expf(s[nt][3] - mn1); rs1 += s[nt][3];
        }
        rs0 += __shfl_xor_sync(0xffffffffu, rs0, 1);
        rs0 += __shfl_xor_sync(0xffffffffu, rs0, 2);
        rs1 += __shfl_xor_sync(0xffffffffu, rs1, 1);
        rs1 += __shfl_xor_sync(0xffffffffu, rs1, 2);
        l0r = l0r * al0 + rs0;
        l1r = l1r * al1 + rs1;

        // stage P (tf32 bits) into per-warp region
        #pragma unroll
        for (int nt = 0; nt < 8; nt++) {
            int cc = nt * 8 + 2 * tig;
            Pw[g * 68 + cc]           = f2tf32(s[nt][0]);
            Pw[g * 68 + cc + 1]       = f2tf32(s[nt][1]);
            Pw[(g + 8) * 68 + cc]     = f2tf32(s[nt][2]);
            Pw[(g + 8) * 68 + cc + 1] = f2tf32(s[nt][3]);
        }
        __syncwarp();

        // O = O*alpha + P @ V
        #pragma unroll
        for (int nt = 0; nt < 8; nt++) {
            o[nt][0] *= al0; o[nt][1] *= al0;
            o[nt][2] *= al1; o[nt][3] *= al1;
        }
        #pragma unroll
        for (int ks = 0; ks < 8; ks++) {
            uint32_t pa[4];
            int kcc = ks * 8 + tig;
            pa[0] = Pw[g * 68 + kcc];     pa[1] = Pw[(g + 8) * 68 + kcc];
            pa[2] = Pw[g * 68 + kcc + 4]; pa[3] = Pw[(g + 8) * 68 + kcc + 4];
            #pragma unroll
            for (int nt = 0; nt < 8; nt++) {
                uint32_t v0 = Vb[(ks * 8 + tig) * 72 + nt * 8 + g];
                uint32_t v1 = Vb[(ks * 8 + tig + 4) * 72 + nt * 8 + g];
                mma_tf32(o[nt], pa, v0, v1);
            }
        }
        __syncthreads();
    }

    // normalize + write ctx
    float inv0 = 1.0f / l0r, inv1 = 1.0f / l1r;
    int row0 = q0 + wq + g;
    #pragma unroll
    for (int nt = 0; nt < 8; nt++) {
        int col = h * 64 + nt * 8 + 2 * tig;
        *(float2*)&g_ctx[(size_t)row0 * E_DIM + col] =
            make_float2(o[nt][0] * inv0, o[nt][1] * inv0);
        *(float2*)&g_ctx[(size_t)(row0 + 8) * E_DIM + col] =
            make_float2(o[nt][2] * inv1, o[nt][3] * inv1);
    }
}

// ---------------- launch ----------------
extern "C" void kernel_launch(void* const* d_in, const int* in_sizes, int n_in,
                              void* d_out, int out_size) {
    const float* hidden = (const float*)d_in[0];
    const float* Wq     = (const float*)d_in[1];
    const float* Wk     = (const float*)d_in[2];
    const float* Wv     = (const float*)d_in[3];
    const float* q2l    = (const float*)d_in[4];
    const float* vup    = (const float*)d_in[5];
    const float* Wout   = (const float*)d_in[6];
    float* out = (float*)d_out;

    void *w1h, *w1l, *w2h, *w2l, *ah, *al, *midp, *ctxp;
    cudaGetSymbolAddress(&w1h, g_W1Th); cudaGetSymbolAddress(&w1l, g_W1Tl);
    cudaGetSymbolAddress(&w2h, g_W2Th); cudaGetSymbolAddress(&w2l, g_W2Tl);
    cudaGetSymbolAddress(&ah,  g_Ah);   cudaGetSymbolAddress(&al,  g_Al);
    cudaGetSymbolAddress(&midp, g_mid); cudaGetSymbolAddress(&ctxp, g_ctx);

    cudaFuncSetAttribute(gemm_mma, cudaFuncAttributeMaxDynamicSharedMemorySize, GEMM_SMEM);
    cudaFuncSetAttribute(attn_mma, cudaFuncAttributeMaxDynamicSharedMemorySize, ATTN_SMEM);

    // weight fusion preps (hi/lo split, transposed [N][K])
    prep_w1_kernel<<<dim3(16, 16), 256>>>(Wq, q2l);
    prep_kv_kernel<<<256, 256>>>(Wk, Wv);
    prep_w2_kernel<<<dim3(16, 16), 256>>>(vup, Wout);

    // split A = hidden
    split_kernel<<<T_SEQ * E_DIM / 1024, 256>>>(hidden, (float*)ah, (float*)al);

    // mid = hidden @ W1 (mode 1: epilogue rounds to tf32, scales q_lat by 0.125)
    gemm_mma<<<dim3(NMID / 128, T_SEQ / 128), 256, GEMM_SMEM>>>(
        (const float*)ah, (const float*)al, (const float*)w1h, (const float*)w1l,
        (float*)midp, NMID, E_DIM, 1);

    // flash attention over latent K/V
    attn_mma<<<dim3(T_SEQ / 128, H_NUM), 256, ATTN_SMEM>>>();

    // split A = ctx
    split_kernel<<<T_SEQ * E_DIM / 1024, 256>>>((const float*)ctxp, (float*)ah, (float*)al);

    // out = ctx @ W2
    gemm_mma<<<dim3(E_DIM / 128, T_SEQ / 128), 256, GEMM_SMEM>>>(
        (const float*)ah, (const float*)al, (const float*)w2h, (const float*)w2l,
        out, E_DIM, E_DIM, 0);
}

// round 8
// speedup vs baseline: 3.1037x; 1.2458x over previous
#include <cuda_runtime.h>
#include <cuda_bf16.h>
#include <cstdint>

#define T_SEQ 2048
#define E_DIM 1024
#define H_NUM 16
#define L_DIM 64
#define NMID  1152   // 1024 q_lat cols + 64 latent_k + 64 latent_v

// ==================== helpers ====================
__device__ __forceinline__ uint32_t f2tf32(float x) {
    uint32_t b;
    asm("cvt.rna.tf32.f32 %0, %1;" : "=r"(b) : "f"(x));
    return b;
}

// tf32: D(16x8) += A(16x8) * B(8x8)
__device__ __forceinline__ void mma_tf32(float* c, const uint32_t* a, uint32_t b0, uint32_t b1) {
    asm volatile(
        "mma.sync.aligned.m16n8k8.row.col.f32.tf32.tf32.f32 "
        "{%0,%1,%2,%3}, {%4,%5,%6,%7}, {%8,%9}, {%0,%1,%2,%3};"
        : "+f"(c[0]), "+f"(c[1]), "+f"(c[2]), "+f"(c[3])
        : "r"(a[0]), "r"(a[1]), "r"(a[2]), "r"(a[3]), "r"(b0), "r"(b1));
}

// bf16: D(16x8) += A(16x16) * B(16x8)
__device__ __forceinline__ void mma_bf16(float* c, const uint32_t* a, uint32_t b0, uint32_t b1) {
    asm volatile(
        "mma.sync.aligned.m16n8k16.row.col.f32.bf16.bf16.f32 "
        "{%0,%1,%2,%3}, {%4,%5,%6,%7}, {%8,%9}, {%0,%1,%2,%3};"
        : "+f"(c[0]), "+f"(c[1]), "+f"(c[2]), "+f"(c[3])
        : "r"(a[0]), "r"(a[1]), "r"(a[2]), "r"(a[3]), "r"(b0), "r"(b1));
}

__device__ __forceinline__ void ldsm_x4(uint32_t& r0, uint32_t& r1, uint32_t& r2, uint32_t& r3,
                                        uint32_t addr) {
    asm volatile("ldmatrix.sync.aligned.m8n8.x4.shared.b16 {%0,%1,%2,%3}, [%4];"
                 : "=r"(r0), "=r"(r1), "=r"(r2), "=r"(r3) : "r"(addr));
}

__device__ __forceinline__ uint32_t smem_u32(const void* p) {
    uint32_t a;
    asm("{ .reg .u64 t; cvta.to.shared.u64 t, %1; cvt.u32.u64 %0, t; }" : "=r"(a) : "l"(p));
    return a;
}

__device__ __forceinline__ void cp_async16(uint32_t dst, const void* src) {
    asm volatile("cp.async.cg.shared.global [%0], [%1], 16;" :: "r"(dst), "l"(src));
}
#define CP_COMMIT()  asm volatile("cp.async.commit_group;" ::: "memory")
#define CP_WAIT(N)   asm volatile("cp.async.wait_group %0;" :: "n"(N) : "memory")

__device__ __forceinline__ void bsplit(float x, __nv_bfloat16& h, __nv_bfloat16& l) {
    h = __float2bfloat16_rn(x);
    l = __float2bfloat16_rn(x - __bfloat162float(h));
}

// ==================== device scratch ====================
__device__ __nv_bfloat16 g_W1Th[NMID * E_DIM], g_W1Tl[NMID * E_DIM];
__device__ __nv_bfloat16 g_W2Th[E_DIM * E_DIM], g_W2Tl[E_DIM * E_DIM];
__device__ __nv_bfloat16 g_Ah[T_SEQ * E_DIM],  g_Al[T_SEQ * E_DIM];
__device__ float g_mid[T_SEQ * NMID];    // [q_lat*0.125 | latent_k | latent_v], tf32-rounded
__device__ float g_ctx[T_SEQ * E_DIM];   // ctx_lat [t, h*64+l], fp32

// ---------------- split A: bf16 hi/lo decomposition ----------------
__global__ __launch_bounds__(256) void split_kernel(const float* __restrict__ src,
                                                    __nv_bfloat16* __restrict__ hi,
                                                    __nv_bfloat16* __restrict__ lo) {
    int i = (blockIdx.x * 256 + threadIdx.x) * 4;
    float4 v = *(const float4*)&src[i];
    __nv_bfloat16 h[4], l[4];
    bsplit(v.x, h[0], l[0]); bsplit(v.y, h[1], l[1]);
    bsplit(v.z, h[2], l[2]); bsplit(v.w, h[3], l[3]);
    *(__nv_bfloat162*)&hi[i]     = __nv_bfloat162{h[0], h[1]};
    *(__nv_bfloat162*)&hi[i + 2] = __nv_bfloat162{h[2], h[3]};
    *(__nv_bfloat162*)&lo[i]     = __nv_bfloat162{l[0], l[1]};
    *(__nv_bfloat162*)&lo[i + 2] = __nv_bfloat162{l[2], l[3]};
}

// ---------------- prep 1: W1T[h*64+l][e] = sum_d Wq[h*64+d, e] * q2l[h,d,l] ----
__global__ __launch_bounds__(256) void prep_w1_kernel(const float* __restrict__ Wq,
                                                      const float* __restrict__ q2l) {
    __shared__ float Wqs[64][65];
    __shared__ float Qls[64][65];
    const int h  = blockIdx.y;
    const int e0 = blockIdx.x * 64;
    const int tid = threadIdx.x, tx = tid & 15, ty = tid >> 4;

    #pragma unroll
    for (int i = 0; i < 16; i++) {
        int lin = tid + i * 256;
        int c = lin & 63, r = lin >> 6;
        Wqs[r][c] = Wq[(h * 64 + r) * E_DIM + e0 + c];
        Qls[r][c] = q2l[(h * 64 + r) * 64 + c];
    }
    __syncthreads();

    float acc[4][4];
    #pragma unroll
    for (int i = 0; i < 4; i++)
        #pragma unroll
        for (int j = 0; j < 4; j++) acc[i][j] = 0.f;

    #pragma unroll 8
    for (int d = 0; d < 64; d++) {
        float a[4], b[4];
        #pragma unroll
        for (int i = 0; i < 4; i++) a[i] = Wqs[d][ty * 4 + i];
        #pragma unroll
        for (int j = 0; j < 4; j++) b[j] = Qls[d][tx * 4 + j];
        #pragma unroll
        for (int i = 0; i < 4; i++)
            #pragma unroll
            for (int j = 0; j < 4; j++) acc[i][j] += a[i] * b[j];
    }
    #pragma unroll
    for (int j = 0; j < 4; j++)
        #pragma unroll
        for (int i = 0; i < 4; i++) {
            int idx = (h * 64 + tx * 4 + j) * E_DIM + e0 + ty * 4 + i;
            __nv_bfloat16 hf, lf; bsplit(acc[i][j], hf, lf);
            g_W1Th[idx] = hf; g_W1Tl[idx] = lf;
        }
}

// ---------------- prep 2: W1T rows 1024+l / 1088+l are Wk_down / Wv_down ----
__global__ __launch_bounds__(256) void prep_kv_kernel(const float* __restrict__ Wk,
                                                      const float* __restrict__ Wv) {
    int idx = blockIdx.x * 256 + threadIdx.x;   // 64 * 1024
    __nv_bfloat16 hf, lf;
    bsplit(Wk[idx], hf, lf);
    g_W1Th[1024 * E_DIM + idx] = hf; g_W1Tl[1024 * E_DIM + idx] = lf;
    bsplit(Wv[idx], hf, lf);
    g_W1Th[1088 * E_DIM + idx] = hf; g_W1Tl[1088 * E_DIM + idx] = lf;
}

// ---------------- prep 3: W2T[e][h*64+l] = sum_d v_up[h,l,d] * Wout[e, h*64+d] ----
__global__ __launch_bounds__(256) void prep_w2_kernel(const float* __restrict__ vup,
                                                      const float* __restrict__ Wout) {
    __shared__ __align__(16) float Wos[64][68];
    __shared__ __align__(16) float Vus[64][68];
    const int h  = blockIdx.y;
    const int e0 = blockIdx.x * 64;
    const int tid = threadIdx.x, tx = tid & 15, ty = tid >> 4;

    #pragma unroll
    for (int i = 0; i < 16; i++) {
        int lin = tid + i * 256;
        int c = lin & 63, r = lin >> 6;
        Wos[r][c] = Wout[(e0 + r) * E_DIM + h * 64 + c];
        Vus[r][c] = vup[(h * 64 + r) * 64 + c];
    }
    __syncthreads();

    float acc[4][4];
    #pragma unroll
    for (int i = 0; i < 4; i++)
        #pragma unroll
        for (int j = 0; j < 4; j++) acc[i][j] = 0.f;

    #pragma unroll
    for (int d4 = 0; d4 < 16; d4++) {
        float4 a[4], b[4];
        #pragma unroll
        for (int i = 0; i < 4; i++) a[i] = *(const float4*)&Vus[ty * 4 + i][d4 * 4];
        #pragma unroll
        for (int j = 0; j < 4; j++) b[j] = *(const float4*)&Wos[tx * 4 + j][d4 * 4];
        #pragma unroll
        for (int i = 0; i < 4; i++)
            #pragma unroll
            for (int j = 0; j < 4; j++)
                acc[i][j] += a[i].x * b[j].x + a[i].y * b[j].y +
                             a[i].z * b[j].z + a[i].w * b[j].w;
    }
    #pragma unroll
    for (int j = 0; j < 4; j++)
        #pragma unroll
        for (int i = 0; i < 4; i++) {
            int idx = (e0 + tx * 4 + j) * E_DIM + h * 64 + ty * 4 + i;
            __nv_bfloat16 hf, lf; bsplit(acc[i][j], hf, lf);
            g_W2Th[idx] = hf; g_W2Tl[idx] = lf;
        }
}

// ==================== bf16 3-term mma.sync GEMM ====================
// C[M,N] = A@BT^T,  A=Ah+Al, BT=Bh+Bl (bf16 tiles).  CTA 128m x 64n, 256 thr
// (8 warps: 4m x 2n; warp tile 32x32).  K-chunk 32 (bf16), 2-stage cp.async,
// rows padded to 80B (conflict-free ldmatrix).  All fragments via ldmatrix.x4.
#define ROWB 80                      // padded row bytes (32 bf16 = 64B data)
#define SA_H 0
#define SA_L (128 * ROWB)            // 10240
#define SB_H (2 * 128 * ROWB)        // 20480
#define SB_L (SB_H + 64 * ROWB)      // 25600
#define SSZ  (SB_L + 64 * ROWB)      // 30720 bytes per stage
#define GEMM_SMEM (2 * SSZ)

__global__ __launch_bounds__(256, 2) void gemm_bf3(const __nv_bfloat16* __restrict__ Ah,
                                                   const __nv_bfloat16* __restrict__ Al,
                                                   const __nv_bfloat16* __restrict__ Bh,
                                                   const __nv_bfloat16* __restrict__ Bl,
                                                   float* __restrict__ C,
                                                   int N, int K, int mode) {
    extern __shared__ char gsm[];
    const uint32_t sbase = smem_u32(gsm);

    const int tid = threadIdx.x;
    const int wid = tid >> 5, lane = tid & 31;
    const int g = lane >> 2, tig = lane & 3;
    const int wm = wid & 3, wn = wid >> 2;
    const int m0 = blockIdx.y * 128;
    const int n0 = blockIdx.x * 64;
    const int nst = K >> 5;

    // ldmatrix lane-address components
    const uint32_t aRow = lane & 15;                    // A/P row within 16
    const uint32_t aSel = ((lane >> 4) & 1) * 16;       // A col-half (bytes)
    const uint32_t bRow = (lane & 7) + ((lane & 16) ? 8 : 0);
    const uint32_t bSel = (lane & 8) ? 16 : 0;

    float c[2][4][4];
    #pragma unroll
    for (int mt = 0; mt < 2; mt++)
        #pragma unroll
        for (int nt = 0; nt < 4; nt++)
            #pragma unroll
            for (int j = 0; j < 4; j++) c[mt][nt][j] = 0.f;

    // fetch stage (1536 16B chunks: Ah 512, Al 512, Bh 256, Bl 256)
    auto fetch = [&](int k0, int b) {
        const uint32_t s0 = sbase + (uint32_t)(b * SSZ);
        #pragma unroll
        for (int i = 0; i < 6; i++) {
            int idx = tid + i * 256;
            if (idx < 1024) {
                int t = idx >> 9;                 // 0=Ah 1=Al
                int r = (idx & 511) >> 2, cc = idx & 3;
                const __nv_bfloat16* src = (t ? Al : Ah) + (size_t)(m0 + r) * K + k0 + cc * 8;
                cp_async16(s0 + (t ? SA_L : SA_H) + r * ROWB + cc * 16, src);
            } else {
                int t = (idx - 1024) >> 8;        // 0=Bh 1=Bl
                int r = ((idx - 1024) & 255) >> 2, cc = idx & 3;
                const __nv_bfloat16* src = (t ? Bl : Bh) + (size_t)(n0 + r) * K + k0 + cc * 8;
                cp_async16(s0 + (t ? SB_L : SB_H) + r * ROWB + cc * 16, src);
            }
        }
        CP_COMMIT();
    };

    fetch(0, 0);

    for (int s = 0; s < nst; s++) {
        const int buf = s & 1;
        if (s + 1 < nst) { fetch((s + 1) << 5, buf ^ 1); CP_WAIT(1); }
        else             { CP_WAIT(0); }
        __syncthreads();

        const uint32_t sb = sbase + (uint32_t)(buf * SSZ);
        #pragma unroll
        for (int ks = 0; ks < 2; ks++) {
            uint32_t ah[2][4], al[2][4];
            #pragma unroll
            for (int mt = 0; mt < 2; mt++) {
                uint32_t ra = (wm * 32 + mt * 16 + aRow) * ROWB + ks * 32 + aSel;
                ldsm_x4(ah[mt][0], ah[mt][1], ah[mt][2], ah[mt][3], sb + SA_H + ra);
                ldsm_x4(al[mt][0], al[mt][1], al[mt][2], al[mt][3], sb + SA_L + ra);
            }
            #pragma unroll
            for (int ntp = 0; ntp < 2; ntp++) {
                uint32_t rb = (wn * 32 + ntp * 16 + bRow) * ROWB + ks * 32 + bSel;
                uint32_t h0, h1, h2, h3, l0, l1, l2, l3;
                ldsm_x4(h0, h1, h2, h3, sb + SB_H + rb);
                ldsm_x4(l0, l1, l2, l3, sb + SB_L + rb);
                #pragma unroll
                for (int mt = 0; mt < 2; mt++) {
                    float* c0 = c[mt][2 * ntp];
                    float* c1 = c[mt][2 * ntp + 1];
                    mma_bf16(c0, ah[mt], h0, h1);
                    mma_bf16(c0, ah[mt], l0, l1);
                    mma_bf16(c0, al[mt], h0, h1);
                    mma_bf16(c1, ah[mt], h2, h3);
                    mma_bf16(c1, ah[mt], l2, l3);
                    mma_bf16(c1, al[mt], h2, h3);
                }
            }
        }
        __syncthreads();
    }

    // epilogue: mode 1 = GEMM1 (round to tf32; scale q_lat cols by 0.125)
    #pragma unroll
    for (int mt = 0; mt < 2; mt++) {
        int row0 = m0 + wm * 32 + mt * 16 + g;
        #pragma unroll
        for (int nt = 0; nt < 4; nt++) {
            int col = n0 + wn * 32 + nt * 8 + 2 * tig;
            float v0 = c[mt][nt][0], v1 = c[mt][nt][1];
            float v2 = c[mt][nt][2], v3 = c[mt][nt][3];
            if (mode == 1) {
                float sc = (col < 1024) ? 0.125f : 1.0f;
                v0 = __uint_as_float(f2tf32(v0 * sc));
                v1 = __uint_as_float(f2tf32(v1 * sc));
                v2 = __uint_as_float(f2tf32(v2 * sc));
                v3 = __uint_as_float(f2tf32(v3 * sc));
            }
            *(float2*)&C[(size_t)row0 * N + col]       = make_float2(v0, v1);
            *(float2*)&C[(size_t)(row0 + 8) * N + col] = make_float2(v2, v3);
        }
    }
}

// ==================== tf32 mma.sync flash attention (ldmatrix) ====================
#define QS_OFF 0
#define KV_OFF (128 * 68)
#define KV_ST  (64 * 68 + 64 * 72)
#define KV_VOFF (64 * 68)
#define PS_OFF (KV_OFF + 2 * KV_ST)
#define ATTN_SMEM ((PS_OFF + 8 * 16 * 68) * 4)

__global__ __launch_bounds__(256, 1) void attn_mma() {
    extern __shared__ uint32_t sm[];
    const uint32_t sbase = smem_u32(sm);
    const int tid = threadIdx.x;
    const int wid = tid >> 5, lane = tid & 31;
    const int g = lane >> 2, tig = lane & 3;
    const int wq = wid * 16;
    const int qt = (int)gridDim.x - 1 - (int)blockIdx.x;  // heavy first
    const int h  = blockIdx.y;
    const int q0 = qt * 128;
    const int nkv = 2 * qt + 2;

    const uint32_t aRow = lane & 15;
    const uint32_t aSel = ((lane >> 4) & 1) * 16;
    const uint32_t bRow = (lane & 7) + ((lane & 16) ? 8 : 0);
    const uint32_t bSel = (lane & 8) ? 16 : 0;

    const int kr[4] = { (tid + 0) >> 4, (tid + 256) >> 4, (tid + 512) >> 4, (tid + 768) >> 4 };
    const int kc = (tid & 15) * 4;

    auto fetch_kv = [&](int blk, int b) {
        #pragma unroll
        for (int i = 0; i < 4; i++) {
            int r = kr[i];
            const float* src = &g_mid[(size_t)(blk * 64 + r) * NMID + 1024 + kc];
            cp_async16(sbase + (uint32_t)(KV_OFF + b * KV_ST + r * 68 + kc) * 4u, src);
            cp_async16(sbase + (uint32_t)(KV_OFF + b * KV_ST + KV_VOFF + r * 72 + kc) * 4u, src + 64);
        }
        CP_COMMIT();
    };

    // prologue: KV block 0 + Q tile
    fetch_kv(0, 0);
    {
        #pragma unroll
        for (int i = 0; i < 8; i++) {
            int lin = tid + i * 256;
            int r = lin >> 4, c4 = lin & 15;
            cp_async16(sbase + (uint32_t)(QS_OFF + r * 68 + c4 * 4) * 4u,
                       &g_mid[(size_t)(q0 + r) * NMID + h * 64 + c4 * 4]);
        }
        CP_COMMIT();
    }
    CP_WAIT(0);
    __syncthreads();

    // preload Q A-fragments via ldmatrix
    uint32_t qa[8][4];
    #pragma unroll
    for (int ks = 0; ks < 8; ks++) {
        uint32_t ra = sbase + (uint32_t)(QS_OFF + (wq + aRow) * 68 + ks * 8) * 4u + aSel;
        ldsm_x4(qa[ks][0], qa[ks][1], qa[ks][2], qa[ks][3], ra);
    }

    float o[8][4];
    #pragma unroll
    for (int nt = 0; nt < 8; nt++)
        #pragma unroll
        for (int j = 0; j < 4; j++) o[nt][j] = 0.f;
    float m0r = -1e30f, m1r = -1e30f, l0r = 0.f, l1r = 0.f;

    const uint32_t pwbase = sbase + (uint32_t)(PS_OFF + wid * 16 * 68) * 4u;
    uint32_t* Pw = &sm[PS_OFF + wid * 16 * 68];

    for (int kb = 0; kb < nkv; kb++) {
        const int buf = kb & 1;
        if (kb + 1 < nkv) { fetch_kv(kb + 1, buf ^ 1); CP_WAIT(1); }
        else              { CP_WAIT(0); }
        __syncthreads();

        const uint32_t kvb = sbase + (uint32_t)(KV_OFF + buf * KV_ST) * 4u;
        const uint32_t* Vb = &sm[KV_OFF + buf * KV_ST + KV_VOFF];
        const int s0 = kb * 64;

        // S = Q @ K^T  (K fragments via ldmatrix.x4, 2 nt per load)
        float s[8][4];
        #pragma unroll
        for (int nt = 0; nt < 8; nt++)
            s[nt][0] = s[nt][1] = s[nt][2] = s[nt][3] = 0.f;
        #pragma unroll
        for (int ntp = 0; ntp < 4; ntp++) {
            #pragma unroll
            for (int ks = 0; ks < 8; ks++) {
                uint32_t addr = kvb + (uint32_t)((ntp * 16 + bRow) * 68 + ks * 8) * 4u + bSel;
                uint32_t k0, k1, k2, k3;
                ldsm_x4(k0, k1, k2, k3, addr);
                mma_tf32(s[2 * ntp],     qa[ks], k0, k1);
                mma_tf32(s[2 * ntp + 1], qa[ks], k2, k3);
            }
        }

        // causal mask (only on last two tiles of this q block)
        if (kb >= 2 * qt) {
            int row0 = q0 + wq + g, row1 = row0 + 8;
            #pragma unroll
            for (int nt = 0; nt < 8; nt++) {
                int c0 = s0 + nt * 8 + 2 * tig;
                if (c0     > row0) s[nt][0] = -1e30f;
                if (c0 + 1 > row0) s[nt][1] = -1e30f;
                if (c0     > row1) s[nt][2] = -1e30f;
                if (c0 + 1 > row1) s[nt][3] = -1e30f;
            }
        }

        // online softmax
        float rm0 = -1e30f, rm1 = -1e30f;
        #pragma unroll
        for (int nt = 0; nt < 8; nt++) {
            rm0 = fmaxf(rm0, fmaxf(s[nt][0], s[nt][1]));
            rm1 = fmaxf(rm1, fmaxf(s[nt][2], s[nt][3]));
        }
        rm0 = fmaxf(rm0, __shfl_xor_sync(0xffffffffu, rm0, 1));
        rm0 = fmaxf(rm0, __shfl_xor_sync(0xffffffffu, rm0, 2));
        rm1 = fmaxf(rm1, __shfl_xor_sync(0xffffffffu, rm1, 1));
        rm1 = fmaxf(rm1, __shfl_xor_sync(0xffffffffu, rm1, 2));
        float mn0 = fmaxf(m0r, rm0), mn1 = fmaxf(m1r, rm1);
        float al0 = __expf(m0r - mn0), al1 = __expf(m1r - mn1);
        m0r = mn0; m1r = mn1;

        float rs0 = 0.f, rs1 = 0.f;
        #pragma unroll
        for (int nt = 0; nt < 8; nt++) {
            s[nt][0] = __expf(s[nt][0] - mn0); rs0 += s[nt][0];
            s[nt][1] = __expf(s[nt][1] - mn0); rs0 += s[nt][1];
            s[nt][2] = __expf(s[nt][2] - mn1); rs1 += s[nt][2];
            s[nt][3] = __expf(s[nt][3] - mn1); rs1 += s[nt][3];
        }
        rs0 += __shfl_xor_sync(0xffffffffu, rs0, 1);
        rs0 += __shfl_xor_sync(0xffffffffu, rs0, 2);
        rs1 += __shfl_xor_sync(0xffffffffu, rs1, 1);
        rs1 += __shfl_xor_sync(0xffffffffu, rs1, 2);
        l0r = l0r * al0 + rs0;
        l1r = l1r * al1 + rs1;

        // stage P (tf32 bits) into per-warp region
        #pragma unroll
        for (int nt = 0; nt < 8; nt++) {
            int cc = nt * 8 + 2 * tig;
            Pw[g * 68 + cc]           = f2tf32(s[nt][0]);
            Pw[g * 68 + cc + 1]       = f2tf32(s[nt][1]);
            Pw[(g + 8) * 68 + cc]     = f2tf32(s[nt][2]);
            Pw[(g + 8) * 68 + cc + 1] = f2tf32(s[nt][3]);
        }
        __syncwarp();

        // O = O*alpha + P @ V   (P via ldmatrix)
        #pragma unroll
        for (int nt = 0; nt < 8; nt++) {
            o[nt][0] *= al0; o[nt][1] *= al0;
            o[nt][2] *= al1; o[nt][3] *= al1;
        }
        #pragma unroll
        for (int ks = 0; ks < 8; ks++) {
            uint32_t pa[4];
            ldsm_x4(pa[0], pa[1], pa[2], pa[3],
                    pwbase + (uint32_t)(aRow * 68 + ks * 8) * 4u + aSel);
            #pragma unroll
            for (int nt = 0; nt < 8; nt++) {
                uint32_t v0 = Vb[(ks * 8 + tig) * 72 + nt * 8 + g];
                uint32_t v1 = Vb[(ks * 8 + tig + 4) * 72 + nt * 8 + g];
                mma_tf32(o[nt], pa, v0, v1);
            }
        }
        __syncthreads();
    }

    // normalize + write ctx
    float inv0 = 1.0f / l0r, inv1 = 1.0f / l1r;
    int row0 = q0 + wq + g;
    #pragma unroll
    for (int nt = 0; nt < 8; nt++) {
        int col = h * 64 + nt * 8 + 2 * tig;
        *(float2*)&g_ctx[(size_t)row0 * E_DIM + col] =
            make_float2(o[nt][0] * inv0, o[nt][1] * inv0);
        *(float2*)&g_ctx[(size_t)(row0 + 8) * E_DIM + col] =
            make_float2(o[nt][2] * inv1, o[nt][3] * inv1);
    }
}

// ---------------- launch ----------------
extern "C" void kernel_launch(void* const* d_in, const int* in_sizes, int n_in,
                              void* d_out, int out_size) {
    const float* hidden = (const float*)d_in[0];
    const float* Wq     = (const float*)d_in[1];
    const float* Wk     = (const float*)d_in[2];
    const float* Wv     = (const float*)d_in[3];
    const float* q2l    = (const float*)d_in[4];
    const float* vup    = (const float*)d_in[5];
    const float* Wout   = (const float*)d_in[6];
    float* out = (float*)d_out;

    void *w1h, *w1l, *w2h, *w2l, *ah, *al, *midp, *ctxp;
    cudaGetSymbolAddress(&w1h, g_W1Th); cudaGetSymbolAddress(&w1l, g_W1Tl);
    cudaGetSymbolAddress(&w2h, g_W2Th); cudaGetSymbolAddress(&w2l, g_W2Tl);
    cudaGetSymbolAddress(&ah,  g_Ah);   cudaGetSymbolAddress(&al,  g_Al);
    cudaGetSymbolAddress(&midp, g_mid); cudaGetSymbolAddress(&ctxp, g_ctx);

    cudaFuncSetAttribute(gemm_bf3, cudaFuncAttributeMaxDynamicSharedMemorySize, GEMM_SMEM);
    cudaFuncSetAttribute(attn_mma, cudaFuncAttributeMaxDynamicSharedMemorySize, ATTN_SMEM);

    // weight fusion preps (bf16 hi/lo, transposed [N][K])
    prep_w1_kernel<<<dim3(16, 16), 256>>>(Wq, q2l);
    prep_kv_kernel<<<256, 256>>>(Wk, Wv);
    prep_w2_kernel<<<dim3(16, 16), 256>>>(vup, Wout);

    // split A = hidden
    split_kernel<<<T_SEQ * E_DIM / 1024, 256>>>(hidden, (__nv_bfloat16*)ah, (__nv_bfloat16*)al);

    // mid = hidden @ W1 (mode 1: epilogue rounds to tf32, scales q_lat by 0.125)
    gemm_bf3<<<dim3(NMID / 64, T_SEQ / 128), 256, GEMM_SMEM>>>(
        (const __nv_bfloat16*)ah, (const __nv_bfloat16*)al,
        (const __nv_bfloat16*)w1h, (const __nv_bfloat16*)w1l,
        (float*)midp, NMID, E_DIM, 1);

    // flash attention over latent K/V
    attn_mma<<<dim3(T_SEQ / 128, H_NUM), 256, ATTN_SMEM>>>();

    // split A = ctx
    split_kernel<<<T_SEQ * E_DIM / 1024, 256>>>((const float*)ctxp,
                                                (__nv_bfloat16*)ah, (__nv_bfloat16*)al);

    // out = ctx @ W2
    gemm_bf3<<<dim3(E_DIM / 64, T_SEQ / 128), 256, GEMM_SMEM>>>(
        (const __nv_bfloat16*)ah, (const __nv_bfloat16*)al,
        (const __nv_bfloat16*)w2h, (const __nv_bfloat16*)w2l,
        out, E_DIM, E_DIM, 0);
}